// round 1
// baseline (speedup 1.0000x reference)
#include <cuda_runtime.h>
#include <cstdint>
#include <math.h>

// Problem constants
#define NB   32
#define CC   128
#define TT   128
#define VV   25
#define TV   3200           // T*V
#define HS   3
#define HT   2
#define CI   32
#define BN_INV 0.9999950000374997f   // 1/sqrt(1+1e-5)

// ---------------- scratch (allocation-free: __device__ globals) ----------------
__device__ float g_qk  [(size_t)NB*192*TV];       // spatial qk  (n,192,t,v)
__device__ float g_atts[(size_t)NB*HS*TT*VV*VV];  // spatial att (n,s,t,u,v)
__device__ float g_y   [(size_t)NB*384*TV];       // spatial mix (n,384,t,v)
__device__ float g_s1  [(size_t)NB*CC*TV];        // s1 / t1 (reused)
__device__ float g_sout[(size_t)NB*CC*TV];        // s_out == z_in
__device__ float g_qkt [(size_t)NB*256*TV];       // temporal qk (n,256,t,v)
__device__ float g_qtm [(size_t)NB*256*TT];       // mean over v (n,256,t)
__device__ float g_attt[(size_t)NB*4*TT*TT];      // temporal att (n,4,t,u)
__device__ float g_z   [(size_t)NB*512*TV];       // temporal mix (n,512,t,v)
__device__ float g_tout[(size_t)NB*CC*TV];        // t_out

// ---------------- generic tiled GEMM with fused epilogue ----------------
// Computes per batch-slice z:  C[m, p] = sum_k A(m,k) * B(k,p),  p in [0,3200)
// AMODE 0: A = W row-major (M,K), shared across z
// AMODE 1: A(m=u, k=t) = att_t[z*T*T + t*T + u]   (z = n*4+s)
// BMODE 0: B(k,p) = Bp[(n*InC + k)*TV + p]
// BMODE 1: B(k=t,p) : c=p/25, v=p%25 -> Bp[((n*128+c)*128 + t)*25 + v]
// BMODE 2: im2col7: c=k/7, j=k%7, t=p/25, v=p%25, tt=t+j-3 (zero pad)
// CMODE 0: out[(n*M + o)*TV + p]
// CMODE 1: o=u, c=p/25, v=p%25 -> out[((n*512 + s*128 + c)*128 + u)*25 + v]
template<int AMODE,int BMODE,int CMODE,bool BIAS,bool BNORM,bool RES,bool LRELU>
__global__ __launch_bounds__(256)
void gemm_kernel(const float* __restrict__ A, const float* __restrict__ Bp,
                 float* __restrict__ Cp,
                 const float* __restrict__ bias, const float* __restrict__ gam,
                 const float* __restrict__ bet, const float* __restrict__ res,
                 int M, int K, int InC)
{
    const int bz = blockIdx.z;
    int n, s;
    if (AMODE==1 || BMODE==1 || CMODE==1) { n = bz >> 2; s = bz & 3; }
    else                                  { n = bz;      s = 0;      }
    const int m0 = blockIdx.y * 64;
    const int p0 = blockIdx.x * 64;

    __shared__ float As[16][68];
    __shared__ float Bs[16][68];

    float acc[4][4] = {};
    const int tid = threadIdx.x;
    const int ty = tid >> 4, tx = tid & 15;

    for (int k0 = 0; k0 < K; k0 += 16) {
        // --- load A tile ---
        #pragma unroll
        for (int r = 0; r < 4; r++) {
            int idx = r*256 + tid;
            if (AMODE == 0) {
                int k = idx & 15, m = idx >> 4;
                As[k][m] = A[(size_t)(m0+m)*K + k0 + k];
            } else {
                int m = idx & 63, k = idx >> 6;
                As[k][m] = A[(size_t)bz*TT*TT + (size_t)(k0+k)*TT + m0 + m];
            }
        }
        // --- load B tile ---
        #pragma unroll
        for (int r = 0; r < 4; r++) {
            int idx = r*256 + tid;
            int p = idx & 63, k = idx >> 6;
            int kk = k0 + k, pp = p0 + p;
            float v;
            if (BMODE == 0) {
                v = Bp[((size_t)n*InC + kk)*TV + pp];
            } else if (BMODE == 1) {
                int c = pp / 25, vv = pp % 25;
                v = Bp[(((size_t)n*CC + c)*TT + kk)*VV + vv];
            } else {
                int c = kk / 7, j = kk % 7;
                int t = pp / 25, vv = pp % 25;
                int t2 = t + j - 3;
                v = (t2 >= 0 && t2 < TT) ? Bp[(((size_t)n*CC + c)*TT + t2)*VV + vv] : 0.f;
            }
            Bs[k][p] = v;
        }
        __syncthreads();
        #pragma unroll
        for (int k = 0; k < 16; k++) {
            float4 av = *(const float4*)&As[k][ty*4];
            float4 bv = *(const float4*)&Bs[k][tx*4];
            float a_[4] = {av.x, av.y, av.z, av.w};
            float b_[4] = {bv.x, bv.y, bv.z, bv.w};
            #pragma unroll
            for (int i = 0; i < 4; i++)
                #pragma unroll
                for (int j = 0; j < 4; j++)
                    acc[i][j] += a_[i] * b_[j];
        }
        __syncthreads();
    }

    // --- epilogue ---
    #pragma unroll
    for (int i = 0; i < 4; i++) {
        int o = m0 + ty*4 + i;
        float bi = BIAS ? bias[o] : 0.f;
        float sc = BNORM ? gam[o]*BN_INV : 1.f;
        float sh = BNORM ? bet[o] : 0.f;
        #pragma unroll
        for (int j = 0; j < 4; j++) {
            int p = p0 + tx*4 + j;
            float v = acc[i][j] + bi;
            if (BNORM) v = v*sc + sh;
            if (RES)   v += res[((size_t)n*CC + o)*TV + p];
            if (LRELU) v = v > 0.f ? v : 0.1f*v;
            size_t oi;
            if (CMODE == 0) {
                oi = ((size_t)n*M + o)*TV + p;
            } else {
                int c = p / 25, vv = p % 25;
                oi = (((size_t)n*512 + s*CC + c)*TT + o)*VV + vv;
            }
            Cp[oi] = v;
        }
    }
}

// ---------------- spatial attention: att[u,v] = bias + tanh(q.k/32)*alpha -------
__global__ __launch_bounds__(256)
void satt_kernel(const float* __restrict__ att0, const float* __restrict__ alphas)
{
    int t = blockIdx.x, s = blockIdx.y, n = blockIdx.z;
    __shared__ float qs[32][25], ks[32][25];
    int tid = threadIdx.x;
    const float* qb = g_qk + ((size_t)n*192 + s*32)*TV + t*VV;
    const float* kb = qb + (size_t)96*TV;
    for (int i = tid; i < 800; i += 256) {
        int c = i / 25, u = i % 25;
        qs[c][u] = qb[(size_t)c*TV + u];
        ks[c][u] = kb[(size_t)c*TV + u];
    }
    __syncthreads();
    float alpha = alphas[s];
    float* ob = g_atts + (((size_t)(n*HS + s))*TT + t)*625;
    for (int idx = tid; idx < 625; idx += 256) {
        int u = idx / 25, v = idx % 25;
        float sum = 0.f;
        #pragma unroll
        for (int c = 0; c < 32; c++) sum += qs[c][u]*ks[c][v];
        ob[idx] = att0[s*625 + idx] + tanhf(sum * (1.f/32.f)) * alpha;
    }
}

// ---------------- spatial mix: y[s,c,t,v] = sum_u x[c,t,u]*att[s,t,u,v] --------
__global__ __launch_bounds__(128)
void ymix_kernel(const float* __restrict__ x)
{
    int t = blockIdx.x, s = blockIdx.y, n = blockIdx.z;
    __shared__ float a[625];
    int c = threadIdx.x;
    const float* ab = g_atts + (((size_t)(n*HS + s))*TT + t)*625;
    for (int i = c; i < 625; i += 128) a[i] = ab[i];
    __syncthreads();
    float xr[25];
    const float* xb = x + ((size_t)n*CC + c)*TV + t*VV;
    #pragma unroll
    for (int u = 0; u < 25; u++) xr[u] = xb[u];
    float accv[25] = {};
    #pragma unroll
    for (int u = 0; u < 25; u++) {
        float xu = xr[u];
        #pragma unroll
        for (int v = 0; v < 25; v++) accv[v] += xu * a[u*25 + v];
    }
    float* yb = g_y + (((size_t)n*384 + s*CC + c)*TT + t)*VV;
    #pragma unroll
    for (int v = 0; v < 25; v++) yb[v] = accv[v];
}

// ---------------- mean over V --------------------------------------------------
__global__ void mean_kernel()
{
    int i = blockIdx.x*blockDim.x + threadIdx.x;    // (n*256+ch)*128 + t
    if (i >= NB*256*TT) return;
    const float* b = g_qkt + (size_t)i*VV;
    float sum = 0.f;
    #pragma unroll
    for (int v = 0; v < 25; v++) sum += b[v];
    g_qtm[i] = sum * (1.f/25.f);
}

// ---------------- temporal attention: tanh(qt.kt/32)*alpha*mask -----------------
__global__ __launch_bounds__(256)
void tatt_kernel(const float* __restrict__ af, const float* __restrict__ ab)
{
    int bz = blockIdx.x;          // n*4 + s
    int n = bz >> 2, s = bz & 3;
    __shared__ float qs[32][128], ks[32][128];
    int tid = threadIdx.x;
    const float* qb = g_qtm + ((size_t)n*256 + s*32)*TT;
    const float* kb = qb + (size_t)128*TT;
    for (int i = tid; i < 4096; i += 256) {
        qs[i >> 7][i & 127] = qb[i];
        ks[i >> 7][i & 127] = kb[i];
    }
    __syncthreads();
    float alpha = (s < HT) ? af[s] : ab[s - HT];
    for (int idx = tid; idx < 16384; idx += 256) {
        int t = idx >> 7, u = idx & 127;
        float sum = 0.f;
        #pragma unroll
        for (int c = 0; c < 32; c++) sum += qs[c][t]*ks[c][u];
        float v = tanhf(sum * (1.f/32.f)) * alpha;
        bool keep = (s < HT) ? (t >= u) : (u >= t);
        g_attt[(size_t)bz*16384 + idx] = keep ? v : 0.f;
    }
}

// ---------------- host launcher -------------------------------------------------
extern "C" void kernel_launch(void* const* d_in, const int* in_sizes, int n_in,
                              void* d_out, int out_size)
{
    const float* x       = (const float*)d_in[0];
    const float* w_in_s  = (const float*)d_in[1];
    const float* b_in_s  = (const float*)d_in[2];
    const float* att0s   = (const float*)d_in[3];
    const float* alphas  = (const float*)d_in[4];
    const float* w_out_s = (const float*)d_in[5];
    const float* b_out_s = (const float*)d_in[6];
    const float* g_out_s = (const float*)d_in[7];
    const float* be_out_s= (const float*)d_in[8];
    const float* w_ff_s  = (const float*)d_in[9];
    const float* b_ff_s  = (const float*)d_in[10];
    const float* g_ff_s  = (const float*)d_in[11];
    const float* be_ff_s = (const float*)d_in[12];
    const float* w_in_t  = (const float*)d_in[13];
    const float* b_in_t  = (const float*)d_in[14];
    const float* al_f    = (const float*)d_in[15];
    const float* al_b    = (const float*)d_in[16];
    const float* w_out_t = (const float*)d_in[17];
    const float* b_out_t = (const float*)d_in[18];
    const float* g_out_t = (const float*)d_in[19];
    const float* be_out_t= (const float*)d_in[20];
    const float* w_ff_t  = (const float*)d_in[21];
    const float* b_ff_t  = (const float*)d_in[22];
    const float* g_ff_t  = (const float*)d_in[23];
    const float* be_ff_t = (const float*)d_in[24];
    const float* w_tcn   = (const float*)d_in[25];
    const float* b_tcn   = (const float*)d_in[26];
    const float* g_tcn   = (const float*)d_in[27];
    const float* be_tcn  = (const float*)d_in[28];
    float* out = (float*)d_out;

    float *qk, *y, *s1, *sout, *qkt, *z, *tout, *attt;
    cudaGetSymbolAddress((void**)&qk,   g_qk);
    cudaGetSymbolAddress((void**)&y,    g_y);
    cudaGetSymbolAddress((void**)&s1,   g_s1);
    cudaGetSymbolAddress((void**)&sout, g_sout);
    cudaGetSymbolAddress((void**)&qkt,  g_qkt);
    cudaGetSymbolAddress((void**)&z,    g_z);
    cudaGetSymbolAddress((void**)&tout, g_tout);
    cudaGetSymbolAddress((void**)&attt, g_attt);

    // 1) spatial qk = conv1x1(x, w_in_s) + b      M=192, K=128
    gemm_kernel<0,0,0,true,false,false,false><<<dim3(50,3,NB),256>>>(
        w_in_s, x, qk, b_in_s, nullptr, nullptr, nullptr, 192, 128, 128);

    // 2) spatial attention
    satt_kernel<<<dim3(TT,HS,NB),256>>>(att0s, alphas);

    // 3) y = x @ att
    ymix_kernel<<<dim3(TT,HS,NB),128>>>(x);

    // 4) s1 = lrelu(x + bn(conv1x1(y, w_out_s)+b))   M=128, K=384
    gemm_kernel<0,0,0,true,true,true,true><<<dim3(50,2,NB),256>>>(
        w_out_s, y, s1, b_out_s, g_out_s, be_out_s, x, 128, 384, 384);

    // 5) s_out = lrelu(x + bn(conv1x1(s1, w_ff_s)+b))  M=128, K=128
    gemm_kernel<0,0,0,true,true,true,true><<<dim3(50,2,NB),256>>>(
        w_ff_s, s1, sout, b_ff_s, g_ff_s, be_ff_s, x, 128, 128, 128);

    // 6) temporal qk = conv1x1(s_out, w_in_t) + b    M=256, K=128
    gemm_kernel<0,0,0,true,false,false,false><<<dim3(50,4,NB),256>>>(
        w_in_t, sout, qkt, b_in_t, nullptr, nullptr, nullptr, 256, 128, 128);

    // 7) mean over V
    mean_kernel<<<(NB*256*TT + 255)/256, 256>>>();

    // 8) temporal attention (tanh + alpha + causal masks)
    tatt_kernel<<<NB*4, 256>>>(al_f, al_b);

    // 9) z[s,c,u,v] = sum_t z_in[c,t,v]*att[t,u]   per (n,s): M=128(u) K=128(t)
    gemm_kernel<1,1,1,false,false,false,false><<<dim3(50,2,NB*4),256>>>(
        attt, sout, z, nullptr, nullptr, nullptr, nullptr, 128, 128, 128);

    // 10) t1 = lrelu(z_in + bn(conv1x1(z, w_out_t)+b))   M=128, K=512
    gemm_kernel<0,0,0,true,true,true,true><<<dim3(50,2,NB),256>>>(
        w_out_t, z, s1, b_out_t, g_out_t, be_out_t, sout, 128, 512, 512);

    // 11) t_out = lrelu(z_in + bn(conv1x1(t1, w_ff_t)+b))  M=128, K=128
    gemm_kernel<0,0,0,true,true,true,true><<<dim3(50,2,NB),256>>>(
        w_ff_t, s1, tout, b_ff_t, g_ff_t, be_ff_t, sout, 128, 128, 128);

    // 12) out = lrelu(t_out + bn(tcn7(t_out)+b))   im2col GEMM  M=128, K=896
    gemm_kernel<0,2,0,true,true,true,true><<<dim3(50,2,NB),256>>>(
        w_tcn, tout, out, b_tcn, g_tcn, be_tcn, tout, 128, 896, 128);
}

// round 2
// speedup vs baseline: 1.0035x; 1.0035x over previous
#include <cuda_runtime.h>
#include <cstdint>
#include <math.h>

// Problem constants
#define NB   32
#define CC   128
#define TT   128
#define VV   25
#define TV   3200           // T*V
#define HS   3
#define HT   2
#define CI   32
#define BN_INV 0.9999950000374997f   // 1/sqrt(1+1e-5)

// ---------------- scratch (allocation-free: __device__ globals) ----------------
__device__ float g_qk  [(size_t)NB*192*TV];       // spatial qk  (n,192,t,v)
__device__ float g_atts[(size_t)NB*HS*TT*VV*VV];  // spatial att (n,s,t,u,v)
__device__ float g_y   [(size_t)NB*384*TV];       // spatial mix (n,384,t,v)
__device__ float g_s1  [(size_t)NB*CC*TV];        // s1 / t1 (reused)
__device__ float g_sout[(size_t)NB*CC*TV];        // s_out == z_in
__device__ float g_qkt [(size_t)NB*256*TV];       // temporal qk (n,256,t,v)
__device__ float g_qtm [(size_t)NB*256*TT];       // mean over v (n,256,t)
__device__ float g_attt[(size_t)NB*4*TT*TT];      // temporal att (n,4,t,u)
__device__ float g_z   [(size_t)NB*512*TV];       // temporal mix (n,512,t,v)
__device__ float g_tout[(size_t)NB*CC*TV];        // t_out

// ---------------- generic tiled GEMM with fused epilogue ----------------
// Computes per batch-slice z:  C[m, p] = sum_k A(m,k) * B(k,p),  p in [0,3200)
// AMODE 0: A = W row-major (M,K), shared across z
// AMODE 1: A(m=u, k=t) = att_t[z*T*T + t*T + u]   (z = n*4+s)
// BMODE 0: B(k,p) = Bp[(n*InC + k)*TV + p]
// BMODE 1: B(k=t,p) : c=p/25, v=p%25 -> Bp[((n*128+c)*128 + t)*25 + v]
// BMODE 2: im2col7: c=k/7, j=k%7, t=p/25, v=p%25, tt=t+j-3 (zero pad)
// CMODE 0: out[(n*M + o)*TV + p]
// CMODE 1: o=u, c=p/25, v=p%25 -> out[((n*512 + s*128 + c)*128 + u)*25 + v]
template<int AMODE,int BMODE,int CMODE,bool BIAS,bool BNORM,bool RES,bool LRELU>
__global__ __launch_bounds__(256)
void gemm_kernel(const float* __restrict__ A, const float* __restrict__ Bp,
                 float* __restrict__ Cp,
                 const float* __restrict__ bias, const float* __restrict__ gam,
                 const float* __restrict__ bet, const float* __restrict__ res,
                 int M, int K, int InC)
{
    const int bz = blockIdx.z;
    int n, s;
    if (AMODE==1 || BMODE==1 || CMODE==1) { n = bz >> 2; s = bz & 3; }
    else                                  { n = bz;      s = 0;      }
    const int m0 = blockIdx.y * 64;
    const int p0 = blockIdx.x * 64;

    __shared__ float As[16][68];
    __shared__ float Bs[16][68];

    float acc[4][4] = {};
    const int tid = threadIdx.x;
    const int ty = tid >> 4, tx = tid & 15;

    for (int k0 = 0; k0 < K; k0 += 16) {
        // --- load A tile ---
        #pragma unroll
        for (int r = 0; r < 4; r++) {
            int idx = r*256 + tid;
            if (AMODE == 0) {
                int k = idx & 15, m = idx >> 4;
                As[k][m] = A[(size_t)(m0+m)*K + k0 + k];
            } else {
                int m = idx & 63, k = idx >> 6;
                As[k][m] = A[(size_t)bz*TT*TT + (size_t)(k0+k)*TT + m0 + m];
            }
        }
        // --- load B tile ---
        #pragma unroll
        for (int r = 0; r < 4; r++) {
            int idx = r*256 + tid;
            int p = idx & 63, k = idx >> 6;
            int kk = k0 + k, pp = p0 + p;
            float v;
            if (BMODE == 0) {
                v = Bp[((size_t)n*InC + kk)*TV + pp];
            } else if (BMODE == 1) {
                int c = pp / 25, vv = pp % 25;
                v = Bp[(((size_t)n*CC + c)*TT + kk)*VV + vv];
            } else {
                int c = kk / 7, j = kk % 7;
                int t = pp / 25, vv = pp % 25;
                int t2 = t + j - 3;
                v = (t2 >= 0 && t2 < TT) ? Bp[(((size_t)n*CC + c)*TT + t2)*VV + vv] : 0.f;
            }
            Bs[k][p] = v;
        }
        __syncthreads();
        #pragma unroll
        for (int k = 0; k < 16; k++) {
            float4 av = *(const float4*)&As[k][ty*4];
            float4 bv = *(const float4*)&Bs[k][tx*4];
            float a_[4] = {av.x, av.y, av.z, av.w};
            float b_[4] = {bv.x, bv.y, bv.z, bv.w};
            #pragma unroll
            for (int i = 0; i < 4; i++)
                #pragma unroll
                for (int j = 0; j < 4; j++)
                    acc[i][j] += a_[i] * b_[j];
        }
        __syncthreads();
    }

    // --- epilogue ---
    #pragma unroll
    for (int i = 0; i < 4; i++) {
        int o = m0 + ty*4 + i;
        float bi = BIAS ? bias[o] : 0.f;
        float sc = BNORM ? gam[o]*BN_INV : 1.f;
        float sh = BNORM ? bet[o] : 0.f;
        #pragma unroll
        for (int j = 0; j < 4; j++) {
            int p = p0 + tx*4 + j;
            float v = acc[i][j] + bi;
            if (BNORM) v = v*sc + sh;
            if (RES)   v += res[((size_t)n*CC + o)*TV + p];
            if (LRELU) v = v > 0.f ? v : 0.1f*v;
            size_t oi;
            if (CMODE == 0) {
                oi = ((size_t)n*M + o)*TV + p;
            } else {
                int c = p / 25, vv = p % 25;
                oi = (((size_t)n*512 + s*CC + c)*TT + o)*VV + vv;
            }
            Cp[oi] = v;
        }
    }
}

// ---------------- spatial attention: att[u,v] = bias + tanh(q.k/32)*alpha -------
__global__ __launch_bounds__(256)
void satt_kernel(const float* __restrict__ att0, const float* __restrict__ alphas)
{
    int t = blockIdx.x, s = blockIdx.y, n = blockIdx.z;
    __shared__ float qs[32][25], ks[32][25];
    int tid = threadIdx.x;
    const float* qb = g_qk + ((size_t)n*192 + s*32)*TV + t*VV;
    const float* kb = qb + (size_t)96*TV;
    for (int i = tid; i < 800; i += 256) {
        int c = i / 25, u = i % 25;
        qs[c][u] = qb[(size_t)c*TV + u];
        ks[c][u] = kb[(size_t)c*TV + u];
    }
    __syncthreads();
    float alpha = alphas[s];
    float* ob = g_atts + (((size_t)(n*HS + s))*TT + t)*625;
    for (int idx = tid; idx < 625; idx += 256) {
        int u = idx / 25, v = idx % 25;
        float sum = 0.f;
        #pragma unroll
        for (int c = 0; c < 32; c++) sum += qs[c][u]*ks[c][v];
        ob[idx] = att0[s*625 + idx] + tanhf(sum * (1.f/32.f)) * alpha;
    }
}

// ---------------- spatial mix: y[s,c,t,v] = sum_u x[c,t,u]*att[s,t,u,v] --------
__global__ __launch_bounds__(128)
void ymix_kernel(const float* __restrict__ x)
{
    int t = blockIdx.x, s = blockIdx.y, n = blockIdx.z;
    __shared__ float a[625];
    int c = threadIdx.x;
    const float* ab = g_atts + (((size_t)(n*HS + s))*TT + t)*625;
    for (int i = c; i < 625; i += 128) a[i] = ab[i];
    __syncthreads();
    float xr[25];
    const float* xb = x + ((size_t)n*CC + c)*TV + t*VV;
    #pragma unroll
    for (int u = 0; u < 25; u++) xr[u] = xb[u];
    float accv[25] = {};
    #pragma unroll
    for (int u = 0; u < 25; u++) {
        float xu = xr[u];
        #pragma unroll
        for (int v = 0; v < 25; v++) accv[v] += xu * a[u*25 + v];
    }
    float* yb = g_y + (((size_t)n*384 + s*CC + c)*TT + t)*VV;
    #pragma unroll
    for (int v = 0; v < 25; v++) yb[v] = accv[v];
}

// ---------------- mean over V --------------------------------------------------
__global__ void mean_kernel()
{
    int i = blockIdx.x*blockDim.x + threadIdx.x;    // (n*256+ch)*128 + t
    if (i >= NB*256*TT) return;
    const float* b = g_qkt + (size_t)i*VV;
    float sum = 0.f;
    #pragma unroll
    for (int v = 0; v < 25; v++) sum += b[v];
    g_qtm[i] = sum * (1.f/25.f);
}

// ---------------- temporal attention: tanh(qt.kt/32)*alpha*mask -----------------
__global__ __launch_bounds__(256)
void tatt_kernel(const float* __restrict__ af, const float* __restrict__ ab)
{
    int bz = blockIdx.x;          // n*4 + s
    int n = bz >> 2, s = bz & 3;
    __shared__ float qs[32][128], ks[32][128];
    int tid = threadIdx.x;
    const float* qb = g_qtm + ((size_t)n*256 + s*32)*TT;
    const float* kb = qb + (size_t)128*TT;
    for (int i = tid; i < 4096; i += 256) {
        qs[i >> 7][i & 127] = qb[i];
        ks[i >> 7][i & 127] = kb[i];
    }
    __syncthreads();
    float alpha = (s < HT) ? af[s] : ab[s - HT];
    for (int idx = tid; idx < 16384; idx += 256) {
        int t = idx >> 7, u = idx & 127;
        float sum = 0.f;
        #pragma unroll
        for (int c = 0; c < 32; c++) sum += qs[c][t]*ks[c][u];
        float v = tanhf(sum * (1.f/32.f)) * alpha;
        bool keep = (s < HT) ? (t >= u) : (u >= t);
        g_attt[(size_t)bz*16384 + idx] = keep ? v : 0.f;
    }
}

// ---------------- host launcher -------------------------------------------------
extern "C" void kernel_launch(void* const* d_in, const int* in_sizes, int n_in,
                              void* d_out, int out_size)
{
    const float* x       = (const float*)d_in[0];
    const float* w_in_s  = (const float*)d_in[1];
    const float* b_in_s  = (const float*)d_in[2];
    const float* att0s   = (const float*)d_in[3];
    const float* alphas  = (const float*)d_in[4];
    const float* w_out_s = (const float*)d_in[5];
    const float* b_out_s = (const float*)d_in[6];
    const float* g_out_s = (const float*)d_in[7];
    const float* be_out_s= (const float*)d_in[8];
    const float* w_ff_s  = (const float*)d_in[9];
    const float* b_ff_s  = (const float*)d_in[10];
    const float* g_ff_s  = (const float*)d_in[11];
    const float* be_ff_s = (const float*)d_in[12];
    const float* w_in_t  = (const float*)d_in[13];
    const float* b_in_t  = (const float*)d_in[14];
    const float* al_f    = (const float*)d_in[15];
    const float* al_b    = (const float*)d_in[16];
    const float* w_out_t = (const float*)d_in[17];
    const float* b_out_t = (const float*)d_in[18];
    const float* g_out_t = (const float*)d_in[19];
    const float* be_out_t= (const float*)d_in[20];
    const float* w_ff_t  = (const float*)d_in[21];
    const float* b_ff_t  = (const float*)d_in[22];
    const float* g_ff_t  = (const float*)d_in[23];
    const float* be_ff_t = (const float*)d_in[24];
    const float* w_tcn   = (const float*)d_in[25];
    const float* b_tcn   = (const float*)d_in[26];
    const float* g_tcn   = (const float*)d_in[27];
    const float* be_tcn  = (const float*)d_in[28];
    float* out = (float*)d_out;

    float *qk, *y, *s1, *sout, *qkt, *z, *tout, *attt;
    cudaGetSymbolAddress((void**)&qk,   g_qk);
    cudaGetSymbolAddress((void**)&y,    g_y);
    cudaGetSymbolAddress((void**)&s1,   g_s1);
    cudaGetSymbolAddress((void**)&sout, g_sout);
    cudaGetSymbolAddress((void**)&qkt,  g_qkt);
    cudaGetSymbolAddress((void**)&z,    g_z);
    cudaGetSymbolAddress((void**)&tout, g_tout);
    cudaGetSymbolAddress((void**)&attt, g_attt);

    // 1) spatial qk = conv1x1(x, w_in_s) + b      M=192, K=128
    gemm_kernel<0,0,0,true,false,false,false><<<dim3(50,3,NB),256>>>(
        w_in_s, x, qk, b_in_s, nullptr, nullptr, nullptr, 192, 128, 128);

    // 2) spatial attention
    satt_kernel<<<dim3(TT,HS,NB),256>>>(att0s, alphas);

    // 3) y = x @ att
    ymix_kernel<<<dim3(TT,HS,NB),128>>>(x);

    // 4) s1 = lrelu(x + bn(conv1x1(y, w_out_s)+b))   M=128, K=384
    gemm_kernel<0,0,0,true,true,true,true><<<dim3(50,2,NB),256>>>(
        w_out_s, y, s1, b_out_s, g_out_s, be_out_s, x, 128, 384, 384);

    // 5) s_out = lrelu(x + bn(conv1x1(s1, w_ff_s)+b))  M=128, K=128
    gemm_kernel<0,0,0,true,true,true,true><<<dim3(50,2,NB),256>>>(
        w_ff_s, s1, sout, b_ff_s, g_ff_s, be_ff_s, x, 128, 128, 128);

    // 6) temporal qk = conv1x1(s_out, w_in_t) + b    M=256, K=128
    gemm_kernel<0,0,0,true,false,false,false><<<dim3(50,4,NB),256>>>(
        w_in_t, sout, qkt, b_in_t, nullptr, nullptr, nullptr, 256, 128, 128);

    // 7) mean over V
    mean_kernel<<<(NB*256*TT + 255)/256, 256>>>();

    // 8) temporal attention (tanh + alpha + causal masks)
    tatt_kernel<<<NB*4, 256>>>(al_f, al_b);

    // 9) z[s,c,u,v] = sum_t z_in[c,t,v]*att[t,u]   per (n,s): M=128(u) K=128(t)
    gemm_kernel<1,1,1,false,false,false,false><<<dim3(50,2,NB*4),256>>>(
        attt, sout, z, nullptr, nullptr, nullptr, nullptr, 128, 128, 128);

    // 10) t1 = lrelu(z_in + bn(conv1x1(z, w_out_t)+b))   M=128, K=512
    gemm_kernel<0,0,0,true,true,true,true><<<dim3(50,2,NB),256>>>(
        w_out_t, z, s1, b_out_t, g_out_t, be_out_t, sout, 128, 512, 512);

    // 11) t_out = lrelu(z_in + bn(conv1x1(t1, w_ff_t)+b))  M=128, K=128
    gemm_kernel<0,0,0,true,true,true,true><<<dim3(50,2,NB),256>>>(
        w_ff_t, s1, tout, b_ff_t, g_ff_t, be_ff_t, sout, 128, 128, 128);

    // 12) out = lrelu(t_out + bn(tcn7(t_out)+b))   im2col GEMM  M=128, K=896
    gemm_kernel<0,2,0,true,true,true,true><<<dim3(50,2,NB),256>>>(
        w_tcn, tout, out, b_tcn, g_tcn, be_tcn, tout, 128, 896, 128);
}

// round 4
// speedup vs baseline: 1.5953x; 1.5898x over previous
#include <cuda_runtime.h>
#include <cstdint>
#include <math.h>

#define NB 32
#define TVn 3200
#define BN_INV 0.9999950000374997f

// ---------------- scratch (__device__ globals; allocation-free) ----------------
__device__ float g_wp  [327680];
__device__ float g_xT  [(size_t)NB*TVn*128];
__device__ float g_qkT [(size_t)NB*TVn*192];
__device__ float g_atts[(size_t)NB*3*128*625];
__device__ float g_yT  [(size_t)NB*TVn*384];
__device__ float g_s1T [(size_t)NB*TVn*128];
__device__ float g_soT [(size_t)NB*TVn*128];
__device__ float g_qktT[(size_t)NB*TVn*256];
__device__ float g_qtm [(size_t)NB*256*128];
__device__ float g_att [(size_t)NB*4*128*128];
__device__ float g_tmaj[(size_t)NB*25*128*128];
__device__ float g_zT  [(size_t)NB*TVn*512];
__device__ float g_toT [(size_t)NB*TVn*128];

// packed weight offsets (elements)
#define OFF_WINS  0
#define OFF_WOUTS 32768
#define OFF_WFFS  81920
#define OFF_WINT  98304
#define OFF_WOUTT 131072
#define OFF_WFFT  196608
#define OFF_WTCN  212992

// ---------------- helpers ----------------
__device__ __forceinline__ uint32_t f2tf32(float f){
    uint32_t r; asm("cvt.rna.tf32.f32 %0, %1;" : "=r"(r) : "f"(f)); return r;
}
__device__ __forceinline__ void mma_tf32(float* d, const uint32_t* a, const uint32_t* b){
    asm volatile("mma.sync.aligned.m16n8k8.row.col.f32.tf32.tf32.f32 "
        "{%0,%1,%2,%3}, {%4,%5,%6,%7}, {%8,%9}, {%0,%1,%2,%3};"
        : "+f"(d[0]), "+f"(d[1]), "+f"(d[2]), "+f"(d[3])
        : "r"(a[0]), "r"(a[1]), "r"(a[2]), "r"(a[3]), "r"(b[0]), "r"(b[1]));
}

// smem layout (uint32 words): As 2 bufs [32][136] at 0; Bs 2 bufs at 8704
__device__ __forceinline__ void sts_tile(uint32_t* sm, int st, int kh, int r,
                                         const float4* la, const float4* lb){
    #pragma unroll
    for (int i = 0; i < 4; i++){
        const float* fa = (const float*)&la[i];
        const float* fb = (const float*)&lb[i];
        #pragma unroll
        for (int j = 0; j < 4; j++){
            int kk = st*32 + kh + i*4 + j;
            sm[kk*136 + r]        = f2tf32(fa[j]);
            sm[8704 + kk*136 + r] = f2tf32(fb[j]);
        }
    }
}

__device__ __forceinline__ void compute_chunk(const uint32_t* sm, int st, int lane,
                                              int wm, int wn, float acc[4][4][4]){
    #pragma unroll
    for (int k8 = 0; k8 < 4; k8++){
        const int kb = st*32 + k8*8 + (lane & 3);
        uint32_t af[4][4], bf[4][2];
        #pragma unroll
        for (int mt = 0; mt < 4; mt++){
            int m = wm + mt*16 + (lane >> 2);
            af[mt][0] = sm[kb*136 + m];
            af[mt][1] = sm[kb*136 + m + 8];
            af[mt][2] = sm[(kb+4)*136 + m];
            af[mt][3] = sm[(kb+4)*136 + m + 8];
        }
        #pragma unroll
        for (int nt = 0; nt < 4; nt++){
            int nn = wn + nt*8 + (lane >> 2);
            bf[nt][0] = sm[8704 + kb*136 + nn];
            bf[nt][1] = sm[8704 + (kb+4)*136 + nn];
        }
        #pragma unroll
        for (int mt = 0; mt < 4; mt++)
            #pragma unroll
            for (int nt = 0; nt < 4; nt++)
                mma_tf32(acc[mt][nt], af[mt], bf[nt]);
    }
}

// ---------------- tensor-core GEMM (mma.sync tf32) ----------------
// D[m, p] = sum_k A[m0+m, k] * B[p, k]
// ZMODE 0: bz=n (A=weights).  ZMODE 1: bz -> (n,s4,v25) temporal mix (A=att[u][t], B=tmaj[c][t]).
// BSHIFT: TCN im2col (chunk c: j=c>>2, B k-col (c&3)*32, row shifted (j-3)*25, zero pad)
// CM 0: write [n][p][ldc]+mg ; CM 1: original NCHW ; CM 2: zT write
template<int ZMODE,int BSHIFT,int CM,bool BIAS,bool BNORM,bool RES,bool LRELU,bool PRED>
__global__ __launch_bounds__(256)
void mma_gemm(const float* __restrict__ A, const float* __restrict__ Bp,
              float* __restrict__ Cp,
              const float* __restrict__ bias, const float* __restrict__ gam,
              const float* __restrict__ bet, const float* __restrict__ resT,
              int Ka, int Bld, int ldc, int Mvalid, int nch)
{
    extern __shared__ uint32_t sm[];
    const int tid = threadIdx.x, lane = tid & 31, wid = tid >> 5;
    const int wm = (wid >> 2) * 64, wn = (wid & 3) * 32;

    int n, s4 = 0, v25 = 0;
    if (ZMODE == 0) { n = blockIdx.z; }
    else { int bz = blockIdx.z; n = bz / 100; int rr = bz % 100; s4 = rr / 25; v25 = rr % 25; }
    const int m0 = blockIdx.y * 128;
    const int p0 = (ZMODE == 0) ? blockIdx.x * 128 : 0;
    const float* Ab = (ZMODE == 0) ? A : A + (size_t)(n*4 + s4) * 16384;
    const float* Bb = (ZMODE == 0) ? Bp + (size_t)n * TVn * Bld
                                   : Bp + (size_t)(n*25 + v25) * 16384;

    const int r = tid & 127, kh = (tid >> 7) * 16;
    const float* parow = Ab + (size_t)(m0 + r) * Ka + kh;

    float acc[4][4][4];
    #pragma unroll
    for (int a = 0; a < 4; a++)
        #pragma unroll
        for (int b = 0; b < 4; b++)
            #pragma unroll
            for (int c = 0; c < 4; c++) acc[a][b][c] = 0.f;

    float4 la[4], lb[4];

    // ---- chunk loader (manually inlined twice) ----
#define GLDG(cc) {                                                              \
        const int k0_ = (cc) * 32;                                              \
        const float4* pa_ = (const float4*)(parow + k0_);                       \
        la[0] = pa_[0]; la[1] = pa_[1]; la[2] = pa_[2]; la[3] = pa_[3];         \
        int k0B_, grow_;                                                        \
        if (BSHIFT){ int j_ = (cc) >> 2; k0B_ = ((cc) & 3) * 32;                \
                     grow_ = p0 + r + (j_ - 3) * 25; }                          \
        else { k0B_ = k0_; grow_ = p0 + r; }                                    \
        const bool ok_ = (!BSHIFT) || ((unsigned)grow_ < (unsigned)TVn);        \
        const float4* pb_ = (const float4*)(Bb + (size_t)(ok_ ? grow_ : 0) * Bld + k0B_ + kh); \
        const float4 zz_ = make_float4(0.f, 0.f, 0.f, 0.f);                     \
        lb[0] = ok_ ? pb_[0] : zz_; lb[1] = ok_ ? pb_[1] : zz_;                 \
        lb[2] = ok_ ? pb_[2] : zz_; lb[3] = ok_ ? pb_[3] : zz_; }

    GLDG(0)
    sts_tile(sm, 0, kh, r, la, lb);
    __syncthreads();

    for (int c = 0; c < nch; c++) {
        const int st = c & 1;
        const bool more = (c + 1 < nch);
        if (more) { GLDG(c + 1) }
        compute_chunk(sm, st, lane, wm, wn, acc);
        if (more) sts_tile(sm, (c + 1) & 1, kh, r, la, lb);
        __syncthreads();
    }
#undef GLDG

    // ---- epilogue ----
    #pragma unroll
    for (int mt = 0; mt < 4; mt++) {
        #pragma unroll
        for (int h = 0; h < 2; h++) {
            const int mloc = wm + mt*16 + (lane >> 2) + h*8;
            const int mg = m0 + mloc;
            if (PRED && mg >= Mvalid) continue;
            float bi = 0.f, sc = 1.f, sh = 0.f;
            if (BIAS) bi = bias[mg];
            if (BNORM){ sc = gam[mg] * BN_INV; sh = bet[mg]; }
            #pragma unroll
            for (int nt = 0; nt < 4; nt++) {
                #pragma unroll
                for (int q = 0; q < 2; q++) {
                    const int col = wn + nt*8 + (lane & 3)*2 + q;
                    float v = acc[mt][nt][h*2 + q] + bi;
                    if (BNORM) v = v * sc + sh;
                    if (RES)   v += resT[((size_t)n*TVn + p0 + col)*128 + mg];
                    if (LRELU) v = v > 0.f ? v : 0.1f * v;
                    if (CM == 0) {
                        Cp[((size_t)n*TVn + p0 + col)*ldc + mg] = v;
                    } else if (CM == 1) {
                        Cp[((size_t)(n*128 + mg))*TVn + p0 + col] = v;
                    } else {
                        Cp[((size_t)n*TVn + (size_t)mloc*25 + v25)*512 + s4*128 + col] = v;
                    }
                }
            }
        }
    }
}

// ---------------- prep: weight pack (pad + tcn reorder) ----------------
__global__ void pack_w(const float* __restrict__ src, float* __restrict__ dst,
                       int Msrc, int Mdst, int K, int tcn)
{
    int idx = blockIdx.x * blockDim.x + threadIdx.x;
    if (idx >= Mdst * K) return;
    int mrow = idx / K, k = idx % K;
    float v = 0.f;
    if (mrow < Msrc) {
        if (tcn) { int j = k >> 7, c = k & 127; v = src[(mrow * 128 + c) * 7 + j]; }
        else     { v = src[(size_t)mrow * K + k]; }
    }
    dst[idx] = v;
}

// ---------------- prep: x -> xT ----------------
__global__ __launch_bounds__(256) void txpose_x(const float* __restrict__ x)
{
    __shared__ float t[32][33];
    int p0 = blockIdx.x * 32, c0 = blockIdx.y * 32, n = blockIdx.z;
    int tx = threadIdx.x & 31, ty = threadIdx.x >> 5;
    for (int r = ty; r < 32; r += 8)
        t[r][tx] = x[((size_t)n * 128 + c0 + r) * TVn + p0 + tx];
    __syncthreads();
    for (int r = ty; r < 32; r += 8)
        g_xT[(size_t)n * TVn * 128 + (size_t)(p0 + r) * 128 + c0 + tx] = t[tx][r];
}

// ---------------- prep: soT -> tmaj[n][v][c][t] ----------------
__global__ __launch_bounds__(256) void txpose_tmaj()
{
    __shared__ float t[32][33];
    int bt = blockIdx.x;
    int t0 = (bt & 3) * 32, c0 = (bt >> 2) * 32;
    int v = blockIdx.y, n = blockIdx.z;
    int tx = threadIdx.x & 31, ty = threadIdx.x >> 5;
    for (int r = ty; r < 32; r += 8)
        t[r][tx] = g_soT[(size_t)n * TVn * 128 + (size_t)((t0 + r) * 25 + v) * 128 + c0 + tx];
    __syncthreads();
    for (int r = ty; r < 32; r += 8)
        g_tmaj[((size_t)(n * 25 + v) * 128 + c0 + r) * 128 + t0 + tx] = t[tx][r];
}

// ---------------- spatial attention ----------------
__global__ __launch_bounds__(256)
void satt_kernel(const float* __restrict__ att0, const float* __restrict__ alphas)
{
    int t = blockIdx.x, s = blockIdx.y, n = blockIdx.z;
    __shared__ float qs[32][25], ks[32][25];
    int tid = threadIdx.x;
    const float* qb = g_qkT + (size_t)n * TVn * 192;
    for (int i = tid; i < 800; i += 256) {
        int c = i / 25, u = i % 25;
        qs[c][u] = qb[(size_t)(t * 25 + u) * 192 + s * 32 + c];
        ks[c][u] = qb[(size_t)(t * 25 + u) * 192 + 96 + s * 32 + c];
    }
    __syncthreads();
    float alpha = alphas[s];
    float* ob = g_atts + (((size_t)(n * 3 + s)) * 128 + t) * 625;
    for (int idx = tid; idx < 625; idx += 256) {
        int u = idx / 25, v = idx % 25;
        float sum = 0.f;
        #pragma unroll
        for (int c = 0; c < 32; c++) sum += qs[c][u] * ks[c][v];
        ob[idx] = att0[s * 625 + idx] + tanhf(sum * (1.f / 32.f)) * alpha;
    }
}

// ---------------- spatial mix -> yT ----------------
__global__ __launch_bounds__(128)
void ymix_kernel(const float* __restrict__ x)
{
    int t = blockIdx.x, s = blockIdx.y, n = blockIdx.z;
    __shared__ float a[625];
    int c = threadIdx.x;
    const float* ab = g_atts + (((size_t)(n * 3 + s)) * 128 + t) * 625;
    for (int i = c; i < 625; i += 128) a[i] = ab[i];
    __syncthreads();
    float xr[25];
    const float* xb = x + ((size_t)n * 128 + c) * TVn + t * 25;
    #pragma unroll
    for (int u = 0; u < 25; u++) xr[u] = xb[u];
    float accv[25] = {};
    #pragma unroll
    for (int u = 0; u < 25; u++) {
        float xu = xr[u];
        #pragma unroll
        for (int v = 0; v < 25; v++) accv[v] += xu * a[u * 25 + v];
    }
    #pragma unroll
    for (int v = 0; v < 25; v++)
        g_yT[(size_t)n * TVn * 384 + (size_t)(t * 25 + v) * 384 + s * 128 + c] = accv[v];
}

// ---------------- mean over V ----------------
__global__ void mean_kernel()
{
    int i = blockIdx.x * blockDim.x + threadIdx.x;
    if (i >= NB * 256 * 128) return;
    int ch = i & 255, t = (i >> 8) & 127, n = i >> 15;
    const float* b = g_qktT + (size_t)n * TVn * 256 + (size_t)(t * 25) * 256 + ch;
    float sum = 0.f;
    #pragma unroll
    for (int v = 0; v < 25; v++) sum += b[v * 256];
    g_qtm[(size_t)n * 32768 + ch * 128 + t] = sum * (1.f / 25.f);
}

// ---------------- temporal attention -> att[u][t] ----------------
__global__ __launch_bounds__(256)
void tatt_kernel(const float* __restrict__ af, const float* __restrict__ ab)
{
    int bz = blockIdx.x;  // n*4 + s
    int n = bz >> 2, s = bz & 3;
    __shared__ float qs[32][128], ks[32][128];
    int tid = threadIdx.x;
    const float* base = g_qtm + (size_t)n * 32768;
    for (int i = tid; i < 4096; i += 256) {
        int c = i >> 7, t = i & 127;
        qs[c][t] = base[(s * 32 + c) * 128 + t];
        ks[c][t] = base[(128 + s * 32 + c) * 128 + t];
    }
    __syncthreads();
    float alpha = (s < 2) ? af[s] : ab[s - 2];
    for (int idx = tid; idx < 16384; idx += 256) {
        int u = idx >> 7, t = idx & 127;
        float sum = 0.f;
        #pragma unroll
        for (int c = 0; c < 32; c++) sum += qs[c][t] * ks[c][u];
        float v = tanhf(sum * (1.f / 32.f)) * alpha;
        bool keep = (s < 2) ? (t >= u) : (u >= t);
        g_att[(size_t)bz * 16384 + idx] = keep ? v : 0.f;  // [u][t]
    }
}

// ---------------- host launcher ----------------
#define SMEMSZ 69632

extern "C" void kernel_launch(void* const* d_in, const int* in_sizes, int n_in,
                              void* d_out, int out_size)
{
    const float* x       = (const float*)d_in[0];
    const float* w_in_s  = (const float*)d_in[1];
    const float* b_in_s  = (const float*)d_in[2];
    const float* att0s   = (const float*)d_in[3];
    const float* alphas  = (const float*)d_in[4];
    const float* w_out_s = (const float*)d_in[5];
    const float* b_out_s = (const float*)d_in[6];
    const float* g_out_s = (const float*)d_in[7];
    const float* be_out_s= (const float*)d_in[8];
    const float* w_ff_s  = (const float*)d_in[9];
    const float* b_ff_s  = (const float*)d_in[10];
    const float* g_ff_s  = (const float*)d_in[11];
    const float* be_ff_s = (const float*)d_in[12];
    const float* w_in_t  = (const float*)d_in[13];
    const float* b_in_t  = (const float*)d_in[14];
    const float* al_f    = (const float*)d_in[15];
    const float* al_b    = (const float*)d_in[16];
    const float* w_out_t = (const float*)d_in[17];
    const float* b_out_t = (const float*)d_in[18];
    const float* g_out_t = (const float*)d_in[19];
    const float* be_out_t= (const float*)d_in[20];
    const float* w_ff_t  = (const float*)d_in[21];
    const float* b_ff_t  = (const float*)d_in[22];
    const float* g_ff_t  = (const float*)d_in[23];
    const float* be_ff_t = (const float*)d_in[24];
    const float* w_tcn   = (const float*)d_in[25];
    const float* b_tcn   = (const float*)d_in[26];
    const float* g_tcn   = (const float*)d_in[27];
    const float* be_tcn  = (const float*)d_in[28];
    float* out = (float*)d_out;

    float *wp, *xT, *qkT, *yT, *s1T, *soT, *qktT, *att, *tmaj, *zT, *toT;
    cudaGetSymbolAddress((void**)&wp,   g_wp);
    cudaGetSymbolAddress((void**)&xT,   g_xT);
    cudaGetSymbolAddress((void**)&qkT,  g_qkT);
    cudaGetSymbolAddress((void**)&yT,   g_yT);
    cudaGetSymbolAddress((void**)&s1T,  g_s1T);
    cudaGetSymbolAddress((void**)&soT,  g_soT);
    cudaGetSymbolAddress((void**)&qktT, g_qktT);
    cudaGetSymbolAddress((void**)&att,  g_att);
    cudaGetSymbolAddress((void**)&tmaj, g_tmaj);
    cudaGetSymbolAddress((void**)&zT,   g_zT);
    cudaGetSymbolAddress((void**)&toT,  g_toT);

    auto G1 = mma_gemm<0,0,0,true,false,false,false,true>;
    auto G2 = mma_gemm<0,0,0,true,true,true,true,false>;
    auto G3 = mma_gemm<0,0,0,true,false,false,false,false>;
    auto G4 = mma_gemm<1,0,2,false,false,false,false,false>;
    auto G5 = mma_gemm<0,1,1,true,true,true,true,false>;
    cudaFuncSetAttribute(G1, cudaFuncAttributeMaxDynamicSharedMemorySize, SMEMSZ);
    cudaFuncSetAttribute(G2, cudaFuncAttributeMaxDynamicSharedMemorySize, SMEMSZ);
    cudaFuncSetAttribute(G3, cudaFuncAttributeMaxDynamicSharedMemorySize, SMEMSZ);
    cudaFuncSetAttribute(G4, cudaFuncAttributeMaxDynamicSharedMemorySize, SMEMSZ);
    cudaFuncSetAttribute(G5, cudaFuncAttributeMaxDynamicSharedMemorySize, SMEMSZ);

    // ---- prep ----
    pack_w<<<(256*128+255)/256,256>>>(w_in_s,  wp+OFF_WINS,  192, 256, 128, 0);
    pack_w<<<(128*384+255)/256,256>>>(w_out_s, wp+OFF_WOUTS, 128, 128, 384, 0);
    pack_w<<<(128*128+255)/256,256>>>(w_ff_s,  wp+OFF_WFFS,  128, 128, 128, 0);
    pack_w<<<(256*128+255)/256,256>>>(w_in_t,  wp+OFF_WINT,  256, 256, 128, 0);
    pack_w<<<(128*512+255)/256,256>>>(w_out_t, wp+OFF_WOUTT, 128, 128, 512, 0);
    pack_w<<<(128*128+255)/256,256>>>(w_ff_t,  wp+OFF_WFFT,  128, 128, 128, 0);
    pack_w<<<(128*896+255)/256,256>>>(w_tcn,   wp+OFF_WTCN,  128, 128, 896, 1);
    txpose_x<<<dim3(100,4,NB),256>>>(x);

    // 1) qk = W_in_s @ x + b   (M padded 256, valid 192)
    G1<<<dim3(25,2,NB),256,SMEMSZ>>>(wp+OFF_WINS, xT, qkT,
        b_in_s, nullptr, nullptr, nullptr, 128, 128, 192, 192, 4);

    // 2) spatial attention
    satt_kernel<<<dim3(128,3,NB),256>>>(att0s, alphas);

    // 3) y = x @ att
    ymix_kernel<<<dim3(128,3,NB),128>>>(x);

    // 4) s1 = lrelu(x + bn(W_out_s @ y + b))   K=384
    G2<<<dim3(25,1,NB),256,SMEMSZ>>>(wp+OFF_WOUTS, yT, s1T,
        b_out_s, g_out_s, be_out_s, xT, 384, 384, 128, 128, 12);

    // 5) sout = lrelu(x + bn(W_ff_s @ s1 + b))
    G2<<<dim3(25,1,NB),256,SMEMSZ>>>(wp+OFF_WFFS, s1T, soT,
        b_ff_s, g_ff_s, be_ff_s, xT, 128, 128, 128, 128, 4);

    // 6) qkt = W_in_t @ sout + b   (M=256)
    G3<<<dim3(25,2,NB),256,SMEMSZ>>>(wp+OFF_WINT, soT, qktT,
        b_in_t, nullptr, nullptr, nullptr, 128, 128, 256, 256, 4);

    // 7) mean over V
    mean_kernel<<<(NB*256*128+255)/256,256>>>();

    // 8) temporal attention
    tatt_kernel<<<NB*4,256>>>(al_f, al_b);

    // prep: sout -> tmaj
    txpose_tmaj<<<dim3(16,25,NB),256>>>();

    // 9) z (temporal mix) per (n,s,v)
    G4<<<dim3(1,1,NB*100),256,SMEMSZ>>>(att, tmaj, zT,
        nullptr, nullptr, nullptr, nullptr, 128, 128, 512, 128, 4);

    // 10) t1 = lrelu(sout + bn(W_out_t @ z + b))   K=512
    G2<<<dim3(25,1,NB),256,SMEMSZ>>>(wp+OFF_WOUTT, zT, s1T,
        b_out_t, g_out_t, be_out_t, soT, 512, 512, 128, 128, 16);

    // 11) tout = lrelu(sout + bn(W_ff_t @ t1 + b))
    G2<<<dim3(25,1,NB),256,SMEMSZ>>>(wp+OFF_WFFT, s1T, toT,
        b_ff_t, g_ff_t, be_ff_t, soT, 128, 128, 128, 128, 4);

    // 12) out = lrelu(tout + bn(tcn7(tout)+b))   K=896 im2col
    G5<<<dim3(25,1,NB),256,SMEMSZ>>>(wp+OFF_WTCN, toT, out,
        b_tcn, g_tcn, be_tcn, toT, 896, 128, 128, 128, 28);
}

// round 5
// speedup vs baseline: 1.9897x; 1.2472x over previous
#include <cuda_runtime.h>
#include <cstdint>
#include <math.h>

#define NB 32
#define TVn 3200
#define BN_INV 0.9999950000374997f

// ---------------- scratch (__device__ globals; allocation-free) ----------------
__device__ float g_wp  [327680];
__device__ float g_xT  [(size_t)NB*TVn*128];
__device__ float g_qkT [(size_t)NB*TVn*192];
__device__ float g_atts[(size_t)NB*3*128*625];
__device__ float g_yT  [(size_t)NB*TVn*384];
__device__ float g_s1T [(size_t)NB*TVn*128];
__device__ float g_soT [(size_t)NB*TVn*128];
__device__ float g_qktT[(size_t)NB*TVn*256];
__device__ float g_qtm [(size_t)NB*256*128];
__device__ float g_att [(size_t)NB*4*128*128];
__device__ float g_tmaj[(size_t)NB*25*128*128];
__device__ float g_zT  [(size_t)NB*TVn*512];
__device__ float g_toT [(size_t)NB*TVn*128];

#define OFF_WINS  0
#define OFF_WOUTS 32768
#define OFF_WFFS  81920
#define OFF_WINT  98304
#define OFF_WOUTT 131072
#define OFF_WFFT  196608
#define OFF_WTCN  212992

// smem geometry (32-bit words): k-group = 4 k-values; per group 128 rows * 4 + 4 pad
#define GRP   516
#define AB_OFF 4128            // B region offset within a stage (8 groups * 516)
#define STG   8256             // words per stage (A 4128 + B 4128)
#define NSTAGE 3
#define SMEMSZ (STG * NSTAGE * 4)   // 99072 bytes

// ---------------- helpers ----------------
__device__ __forceinline__ uint32_t smem_u32(const void* p){
    uint32_t a;
    asm("{ .reg .u64 t; cvta.to.shared.u64 t, %1; cvt.u32.u64 %0, t; }" : "=r"(a) : "l"(p));
    return a;
}
__device__ __forceinline__ uint32_t f2tf32(float f){
    uint32_t r; asm("cvt.rna.tf32.f32 %0, %1;" : "=r"(r) : "f"(f)); return r;
}
__device__ __forceinline__ void mma_tf32(float* d, const uint32_t* a, const uint32_t* b){
    asm volatile("mma.sync.aligned.m16n8k8.row.col.f32.tf32.tf32.f32 "
        "{%0,%1,%2,%3}, {%4,%5,%6,%7}, {%8,%9}, {%0,%1,%2,%3};"
        : "+f"(d[0]), "+f"(d[1]), "+f"(d[2]), "+f"(d[3])
        : "r"(a[0]), "r"(a[1]), "r"(a[2]), "r"(a[3]), "r"(b[0]), "r"(b[1]));
}

__device__ __forceinline__ void compute_chunk(const uint32_t* sm, int stg, int lane,
                                              int wm, int wn, float acc[4][4][4]){
    const int klo = lane & 3, lq = lane >> 2;
    const int base = stg * STG;
    #pragma unroll
    for (int k8 = 0; k8 < 4; k8++){
        const int a0 = base + (k8*2)*GRP + klo;
        const int b0 = base + AB_OFF + (k8*2)*GRP + klo;
        uint32_t af[4][4], bf[4][2];
        #pragma unroll
        for (int mt = 0; mt < 4; mt++){
            const int mo = (wm + mt*16 + lq) * 4;
            af[mt][0] = sm[a0 + mo];
            af[mt][1] = sm[a0 + mo + 32];
            af[mt][2] = sm[a0 + GRP + mo];
            af[mt][3] = sm[a0 + GRP + mo + 32];
        }
        #pragma unroll
        for (int nt = 0; nt < 4; nt++){
            const int no = (wn + nt*8 + lq) * 4;
            bf[nt][0] = sm[b0 + no];
            bf[nt][1] = sm[b0 + GRP + no];
        }
        #pragma unroll
        for (int mt = 0; mt < 4; mt++)
            #pragma unroll
            for (int nt = 0; nt < 4; nt++)
                mma_tf32(acc[mt][nt], af[mt], bf[nt]);
    }
}

// ---------------- tensor-core GEMM (mma.sync tf32, cp.async 3-stage) ----------------
// D[m, p] = sum_k A[m0+m, k] * B[p, k]
// ZMODE 0: bz=n (A=weights).  ZMODE 1: bz -> (n,s4,v25) temporal mix.
// BSHIFT: TCN im2col (chunk c: j=c>>2, B k-col (c&3)*32, row shifted (j-3)*25, zfill)
// CM 0: [n][p][ldc]+mg ; CM 1: original NCHW ; CM 2: zT write
template<int ZMODE,int BSHIFT,int CM,bool BIAS,bool BNORM,bool RES,bool LRELU,bool PRED>
__global__ __launch_bounds__(256,2)
void mma_gemm(const float* __restrict__ A, const float* __restrict__ Bp,
              float* __restrict__ Cp,
              const float* __restrict__ bias, const float* __restrict__ gam,
              const float* __restrict__ bet, const float* __restrict__ resT,
              int Ka, int Bld, int ldc, int Mvalid, int nch)
{
    extern __shared__ uint32_t sm[];
    const uint32_t sbw = smem_u32(sm);
    const int tid = threadIdx.x, lane = tid & 31, wid = tid >> 5;
    const int wm = (wid >> 2) * 64, wn = (wid & 3) * 32;

    int n, s4 = 0, v25 = 0;
    if (ZMODE == 0) { n = blockIdx.z; }
    else { int bz = blockIdx.z; n = bz / 100; int rr = bz % 100; s4 = rr / 25; v25 = rr % 25; }
    const int m0 = blockIdx.y * 128;
    const int p0 = (ZMODE == 0) ? blockIdx.x * 128 : 0;
    const float* Ab = (ZMODE == 0) ? A : A + (size_t)(n*4 + s4) * 16384;
    const float* Bb = (ZMODE == 0) ? Bp + (size_t)n * TVn * Bld
                                   : Bp + (size_t)(n*25 + v25) * 16384;

    const int r = tid & 127, kh = (tid >> 7) * 16, g0 = (tid >> 7) * 4;
    const float* parow = Ab + (size_t)(m0 + r) * Ka + kh;

    float acc[4][4][4];
    #pragma unroll
    for (int a = 0; a < 4; a++)
        #pragma unroll
        for (int b = 0; b < 4; b++)
            #pragma unroll
            for (int c = 0; c < 4; c++) acc[a][b][c] = 0.f;

    // issue loads for chunk cc into stage stg
#define ISSUE(cc, stg) {                                                         \
        const int k0_ = (cc) * 32;                                               \
        int k0B_, grow_;                                                         \
        if (BSHIFT){ int j_ = (cc) >> 2; k0B_ = ((cc) & 3) * 32;                 \
                     grow_ = p0 + r + (j_ - 3) * 25; }                           \
        else { k0B_ = k0_; grow_ = p0 + r; }                                     \
        const bool ok_ = (!BSHIFT) || ((unsigned)grow_ < (unsigned)TVn);         \
        const int bsz_ = ok_ ? 16 : 0;                                           \
        const float* asrc_ = parow + k0_;                                        \
        const float* bsrc_ = Bb + (size_t)(ok_ ? grow_ : 0) * Bld + k0B_ + kh;   \
        const uint32_t ad_ = sbw + 4u * ((stg) * STG + g0 * GRP + r * 4);        \
        const uint32_t bd_ = ad_ + 4u * AB_OFF;                                  \
        _Pragma("unroll")                                                        \
        for (int i = 0; i < 4; i++){                                             \
            asm volatile("cp.async.cg.shared.global [%0], [%1], 16;"             \
                         :: "r"(ad_ + 4u*i*GRP), "l"(asrc_ + i*4) : "memory");   \
            asm volatile("cp.async.cg.shared.global [%0], [%1], 16, %2;"         \
                         :: "r"(bd_ + 4u*i*GRP), "l"(bsrc_ + i*4), "r"(bsz_) : "memory"); \
        } }

    ISSUE(0, 0)
    asm volatile("cp.async.commit_group;" ::: "memory");
    ISSUE(1, 1)
    asm volatile("cp.async.commit_group;" ::: "memory");

    for (int c = 0; c < nch; c++) {
        asm volatile("cp.async.wait_group 1;" ::: "memory");
        __syncthreads();
        compute_chunk(sm, c % NSTAGE, lane, wm, wn, acc);
        const int nc = c + 2;
        if (nc < nch) { ISSUE(nc, nc % NSTAGE) }
        asm volatile("cp.async.commit_group;" ::: "memory");
    }
#undef ISSUE

    // ---- epilogue ----
    #pragma unroll
    for (int mt = 0; mt < 4; mt++) {
        #pragma unroll
        for (int h = 0; h < 2; h++) {
            const int mloc = wm + mt*16 + (lane >> 2) + h*8;
            const int mg = m0 + mloc;
            if (PRED && mg >= Mvalid) continue;
            float bi = 0.f, sc = 1.f, sh = 0.f;
            if (BIAS) bi = bias[mg];
            if (BNORM){ sc = gam[mg] * BN_INV; sh = bet[mg]; }
            #pragma unroll
            for (int nt = 0; nt < 4; nt++) {
                #pragma unroll
                for (int q = 0; q < 2; q++) {
                    const int col = wn + nt*8 + (lane & 3)*2 + q;
                    float v = acc[mt][nt][h*2 + q] + bi;
                    if (BNORM) v = v * sc + sh;
                    if (RES)   v += resT[((size_t)n*TVn + p0 + col)*128 + mg];
                    if (LRELU) v = v > 0.f ? v : 0.1f * v;
                    if (CM == 0) {
                        Cp[((size_t)n*TVn + p0 + col)*ldc + mg] = v;
                    } else if (CM == 1) {
                        Cp[((size_t)(n*128 + mg))*TVn + p0 + col] = v;
                    } else {
                        Cp[((size_t)n*TVn + (size_t)mloc*25 + v25)*512 + s4*128 + col] = v;
                    }
                }
            }
        }
    }
}

// ---------------- prep: weight pack (pad + tcn reorder + tf32 round) ----------------
__global__ void pack_w(const float* __restrict__ src, float* __restrict__ dst,
                       int Msrc, int Mdst, int K, int tcn)
{
    int idx = blockIdx.x * blockDim.x + threadIdx.x;
    if (idx >= Mdst * K) return;
    int mrow = idx / K, k = idx % K;
    float v = 0.f;
    if (mrow < Msrc) {
        if (tcn) { int j = k >> 7, c = k & 127; v = src[(mrow * 128 + c) * 7 + j]; }
        else     { v = src[(size_t)mrow * K + k]; }
    }
    dst[idx] = __uint_as_float(f2tf32(v));
}

// ---------------- prep: x -> xT ----------------
__global__ __launch_bounds__(256) void txpose_x(const float* __restrict__ x)
{
    __shared__ float t[32][33];
    int p0 = blockIdx.x * 32, c0 = blockIdx.y * 32, n = blockIdx.z;
    int tx = threadIdx.x & 31, ty = threadIdx.x >> 5;
    for (int r = ty; r < 32; r += 8)
        t[r][tx] = x[((size_t)n * 128 + c0 + r) * TVn + p0 + tx];
    __syncthreads();
    for (int r = ty; r < 32; r += 8)
        g_xT[(size_t)n * TVn * 128 + (size_t)(p0 + r) * 128 + c0 + tx] = t[tx][r];
}

// ---------------- prep: soT -> tmaj[n][v][c][t] ----------------
__global__ __launch_bounds__(256) void txpose_tmaj()
{
    __shared__ float t[32][33];
    int bt = blockIdx.x;
    int t0 = (bt & 3) * 32, c0 = (bt >> 2) * 32;
    int v = blockIdx.y, n = blockIdx.z;
    int tx = threadIdx.x & 31, ty = threadIdx.x >> 5;
    for (int r = ty; r < 32; r += 8)
        t[r][tx] = g_soT[(size_t)n * TVn * 128 + (size_t)((t0 + r) * 25 + v) * 128 + c0 + tx];
    __syncthreads();
    for (int r = ty; r < 32; r += 8)
        g_tmaj[((size_t)(n * 25 + v) * 128 + c0 + r) * 128 + t0 + tx] = t[tx][r];
}

// ---------------- spatial attention ----------------
__global__ __launch_bounds__(256)
void satt_kernel(const float* __restrict__ att0, const float* __restrict__ alphas)
{
    int t = blockIdx.x, s = blockIdx.y, n = blockIdx.z;
    __shared__ float qs[32][25], ks[32][25];
    int tid = threadIdx.x;
    const float* qb = g_qkT + (size_t)n * TVn * 192;
    for (int i = tid; i < 800; i += 256) {
        int c = i / 25, u = i % 25;
        qs[c][u] = qb[(size_t)(t * 25 + u) * 192 + s * 32 + c];
        ks[c][u] = qb[(size_t)(t * 25 + u) * 192 + 96 + s * 32 + c];
    }
    __syncthreads();
    float alpha = alphas[s];
    float* ob = g_atts + (((size_t)(n * 3 + s)) * 128 + t) * 625;
    for (int idx = tid; idx < 625; idx += 256) {
        int u = idx / 25, v = idx % 25;
        float sum = 0.f;
        #pragma unroll
        for (int c = 0; c < 32; c++) sum += qs[c][u] * ks[c][v];
        ob[idx] = att0[s * 625 + idx] + tanhf(sum * (1.f / 32.f)) * alpha;
    }
}

// ---------------- spatial mix -> yT ----------------
__global__ __launch_bounds__(128)
void ymix_kernel(const float* __restrict__ x)
{
    int t = blockIdx.x, s = blockIdx.y, n = blockIdx.z;
    __shared__ float a[625];
    int c = threadIdx.x;
    const float* ab = g_atts + (((size_t)(n * 3 + s)) * 128 + t) * 625;
    for (int i = c; i < 625; i += 128) a[i] = ab[i];
    __syncthreads();
    float xr[25];
    const float* xb = x + ((size_t)n * 128 + c) * TVn + t * 25;
    #pragma unroll
    for (int u = 0; u < 25; u++) xr[u] = xb[u];
    float accv[25] = {};
    #pragma unroll
    for (int u = 0; u < 25; u++) {
        float xu = xr[u];
        #pragma unroll
        for (int v = 0; v < 25; v++) accv[v] += xu * a[u * 25 + v];
    }
    #pragma unroll
    for (int v = 0; v < 25; v++)
        g_yT[(size_t)n * TVn * 384 + (size_t)(t * 25 + v) * 384 + s * 128 + c] = accv[v];
}

// ---------------- mean over V ----------------
__global__ void mean_kernel()
{
    int i = blockIdx.x * blockDim.x + threadIdx.x;
    if (i >= NB * 256 * 128) return;
    int ch = i & 255, t = (i >> 8) & 127, n = i >> 15;
    const float* b = g_qktT + (size_t)n * TVn * 256 + (size_t)(t * 25) * 256 + ch;
    float sum = 0.f;
    #pragma unroll
    for (int v = 0; v < 25; v++) sum += b[v * 256];
    g_qtm[(size_t)n * 32768 + ch * 128 + t] = sum * (1.f / 25.f);
}

// ---------------- temporal attention -> att[u][t] ----------------
__global__ __launch_bounds__(256)
void tatt_kernel(const float* __restrict__ af, const float* __restrict__ ab)
{
    int bz = blockIdx.x;  // n*4 + s
    int n = bz >> 2, s = bz & 3;
    __shared__ float qs[32][128], ks[32][128];
    int tid = threadIdx.x;
    const float* base = g_qtm + (size_t)n * 32768;
    for (int i = tid; i < 4096; i += 256) {
        int c = i >> 7, t = i & 127;
        qs[c][t] = base[(s * 32 + c) * 128 + t];
        ks[c][t] = base[(128 + s * 32 + c) * 128 + t];
    }
    __syncthreads();
    float alpha = (s < 2) ? af[s] : ab[s - 2];
    for (int idx = tid; idx < 16384; idx += 256) {
        int u = idx >> 7, t = idx & 127;
        float sum = 0.f;
        #pragma unroll
        for (int c = 0; c < 32; c++) sum += qs[c][t] * ks[c][u];
        float v = tanhf(sum * (1.f / 32.f)) * alpha;
        bool keep = (s < 2) ? (t >= u) : (u >= t);
        g_att[(size_t)bz * 16384 + idx] = keep ? v : 0.f;  // [u][t]
    }
}

// ---------------- host launcher ----------------
extern "C" void kernel_launch(void* const* d_in, const int* in_sizes, int n_in,
                              void* d_out, int out_size)
{
    const float* x       = (const float*)d_in[0];
    const float* w_in_s  = (const float*)d_in[1];
    const float* b_in_s  = (const float*)d_in[2];
    const float* att0s   = (const float*)d_in[3];
    const float* alphas  = (const float*)d_in[4];
    const float* w_out_s = (const float*)d_in[5];
    const float* b_out_s = (const float*)d_in[6];
    const float* g_out_s = (const float*)d_in[7];
    const float* be_out_s= (const float*)d_in[8];
    const float* w_ff_s  = (const float*)d_in[9];
    const float* b_ff_s  = (const float*)d_in[10];
    const float* g_ff_s  = (const float*)d_in[11];
    const float* be_ff_s = (const float*)d_in[12];
    const float* w_in_t  = (const float*)d_in[13];
    const float* b_in_t  = (const float*)d_in[14];
    const float* al_f    = (const float*)d_in[15];
    const float* al_b    = (const float*)d_in[16];
    const float* w_out_t = (const float*)d_in[17];
    const float* b_out_t = (const float*)d_in[18];
    const float* g_out_t = (const float*)d_in[19];
    const float* be_out_t= (const float*)d_in[20];
    const float* w_ff_t  = (const float*)d_in[21];
    const float* b_ff_t  = (const float*)d_in[22];
    const float* g_ff_t  = (const float*)d_in[23];
    const float* be_ff_t = (const float*)d_in[24];
    const float* w_tcn   = (const float*)d_in[25];
    const float* b_tcn   = (const float*)d_in[26];
    const float* g_tcn   = (const float*)d_in[27];
    const float* be_tcn  = (const float*)d_in[28];
    float* out = (float*)d_out;

    float *wp, *xT, *qkT, *yT, *s1T, *soT, *qktT, *att, *tmaj, *zT, *toT;
    cudaGetSymbolAddress((void**)&wp,   g_wp);
    cudaGetSymbolAddress((void**)&xT,   g_xT);
    cudaGetSymbolAddress((void**)&qkT,  g_qkT);
    cudaGetSymbolAddress((void**)&yT,   g_yT);
    cudaGetSymbolAddress((void**)&s1T,  g_s1T);
    cudaGetSymbolAddress((void**)&soT,  g_soT);
    cudaGetSymbolAddress((void**)&qktT, g_qktT);
    cudaGetSymbolAddress((void**)&att,  g_att);
    cudaGetSymbolAddress((void**)&tmaj, g_tmaj);
    cudaGetSymbolAddress((void**)&zT,   g_zT);
    cudaGetSymbolAddress((void**)&toT,  g_toT);

    auto G1 = mma_gemm<0,0,0,true,false,false,false,true>;
    auto G2 = mma_gemm<0,0,0,true,true,true,true,false>;
    auto G3 = mma_gemm<0,0,0,true,false,false,false,false>;
    auto G4 = mma_gemm<1,0,2,false,false,false,false,false>;
    auto G5 = mma_gemm<0,1,1,true,true,true,true,false>;
    cudaFuncSetAttribute(G1, cudaFuncAttributeMaxDynamicSharedMemorySize, SMEMSZ);
    cudaFuncSetAttribute(G2, cudaFuncAttributeMaxDynamicSharedMemorySize, SMEMSZ);
    cudaFuncSetAttribute(G3, cudaFuncAttributeMaxDynamicSharedMemorySize, SMEMSZ);
    cudaFuncSetAttribute(G4, cudaFuncAttributeMaxDynamicSharedMemorySize, SMEMSZ);
    cudaFuncSetAttribute(G5, cudaFuncAttributeMaxDynamicSharedMemorySize, SMEMSZ);

    // ---- prep ----
    pack_w<<<(256*128+255)/256,256>>>(w_in_s,  wp+OFF_WINS,  192, 256, 128, 0);
    pack_w<<<(128*384+255)/256,256>>>(w_out_s, wp+OFF_WOUTS, 128, 128, 384, 0);
    pack_w<<<(128*128+255)/256,256>>>(w_ff_s,  wp+OFF_WFFS,  128, 128, 128, 0);
    pack_w<<<(256*128+255)/256,256>>>(w_in_t,  wp+OFF_WINT,  256, 256, 128, 0);
    pack_w<<<(128*512+255)/256,256>>>(w_out_t, wp+OFF_WOUTT, 128, 128, 512, 0);
    pack_w<<<(128*128+255)/256,256>>>(w_ff_t,  wp+OFF_WFFT,  128, 128, 128, 0);
    pack_w<<<(128*896+255)/256,256>>>(w_tcn,   wp+OFF_WTCN,  128, 128, 896, 1);
    txpose_x<<<dim3(100,4,NB),256>>>(x);

    // 1) qk = W_in_s @ x + b   (M padded 256, valid 192)
    G1<<<dim3(25,2,NB),256,SMEMSZ>>>(wp+OFF_WINS, xT, qkT,
        b_in_s, nullptr, nullptr, nullptr, 128, 128, 192, 192, 4);

    // 2) spatial attention
    satt_kernel<<<dim3(128,3,NB),256>>>(att0s, alphas);

    // 3) y = x @ att
    ymix_kernel<<<dim3(128,3,NB),128>>>(x);

    // 4) s1 = lrelu(x + bn(W_out_s @ y + b))   K=384
    G2<<<dim3(25,1,NB),256,SMEMSZ>>>(wp+OFF_WOUTS, yT, s1T,
        b_out_s, g_out_s, be_out_s, xT, 384, 384, 128, 128, 12);

    // 5) sout = lrelu(x + bn(W_ff_s @ s1 + b))
    G2<<<dim3(25,1,NB),256,SMEMSZ>>>(wp+OFF_WFFS, s1T, soT,
        b_ff_s, g_ff_s, be_ff_s, xT, 128, 128, 128, 128, 4);

    // 6) qkt = W_in_t @ sout + b   (M=256)
    G3<<<dim3(25,2,NB),256,SMEMSZ>>>(wp+OFF_WINT, soT, qktT,
        b_in_t, nullptr, nullptr, nullptr, 128, 128, 256, 256, 4);

    // 7) mean over V
    mean_kernel<<<(NB*256*128+255)/256,256>>>();

    // 8) temporal attention
    tatt_kernel<<<NB*4,256>>>(al_f, al_b);

    // prep: sout -> tmaj
    txpose_tmaj<<<dim3(16,25,NB),256>>>();

    // 9) z (temporal mix) per (n,s,v)
    G4<<<dim3(1,1,NB*100),256,SMEMSZ>>>(att, tmaj, zT,
        nullptr, nullptr, nullptr, nullptr, 128, 128, 512, 128, 4);

    // 10) t1 = lrelu(sout + bn(W_out_t @ z + b))   K=512
    G2<<<dim3(25,1,NB),256,SMEMSZ>>>(wp+OFF_WOUTT, zT, s1T,
        b_out_t, g_out_t, be_out_t, soT, 512, 512, 128, 128, 16);

    // 11) tout = lrelu(sout + bn(W_ff_t @ t1 + b))
    G2<<<dim3(25,1,NB),256,SMEMSZ>>>(wp+OFF_WFFT, s1T, toT,
        b_ff_t, g_ff_t, be_ff_t, soT, 128, 128, 128, 128, 4);

    // 12) out = lrelu(tout + bn(tcn7(tout)+b))   K=896 im2col
    G5<<<dim3(25,1,NB),256,SMEMSZ>>>(wp+OFF_WTCN, toT, out,
        b_tcn, g_tcn, be_tcn, toT, 896, 128, 128, 128, 28);
}

// round 6
// speedup vs baseline: 2.4520x; 1.2323x over previous
#include <cuda_runtime.h>
#include <cstdint>
#include <math.h>

#define NB 32
#define TVn 3200
#define BN_INV 0.9999950000374997f

// ---------------- scratch (__device__ globals; allocation-free) ----------------
__device__ float g_wp  [327680];
__device__ float g_xT  [(size_t)NB*TVn*128];
__device__ float g_qkT [(size_t)NB*TVn*192];
__device__ float g_atts[(size_t)NB*3*128*625];
__device__ float g_yT  [(size_t)NB*TVn*384];
__device__ float g_s1T [(size_t)NB*TVn*128];
__device__ float g_soT [(size_t)NB*TVn*128];
__device__ float g_sbar[(size_t)NB*128*128];
__device__ float g_qtm [(size_t)NB*128*256];
__device__ float g_att [(size_t)NB*4*128*128];
__device__ float g_tmaj[(size_t)NB*25*128*128];
__device__ float g_zT  [(size_t)NB*TVn*512];
__device__ float g_toT [(size_t)NB*TVn*128];
__device__ float g_tnc [(size_t)NB*128*TVn];

#define OFF_WINS  0
#define OFF_WOUTS 32768
#define OFF_WFFS  81920
#define OFF_WINT  98304
#define OFF_WOUTT 131072
#define OFF_WFFT  196608
#define OFF_WTCN  212992

// smem geometry (32-bit words): k-group = 4 k-values; per group 128 rows * 4 + 4 pad
#define GRP   516
#define AB_OFF 4128
#define STG   8256
#define NSTAGE 3
#define SMEMSZ (STG * NSTAGE * 4)   // 99072 bytes

// ---------------- helpers ----------------
__device__ __forceinline__ uint32_t smem_u32(const void* p){
    uint32_t a;
    asm("{ .reg .u64 t; cvta.to.shared.u64 t, %1; cvt.u32.u64 %0, t; }" : "=r"(a) : "l"(p));
    return a;
}
__device__ __forceinline__ uint32_t f2tf32(float f){
    uint32_t r; asm("cvt.rna.tf32.f32 %0, %1;" : "=r"(r) : "f"(f)); return r;
}
__device__ __forceinline__ void mma_tf32(float* d, const uint32_t* a, const uint32_t* b){
    asm volatile("mma.sync.aligned.m16n8k8.row.col.f32.tf32.tf32.f32 "
        "{%0,%1,%2,%3}, {%4,%5,%6,%7}, {%8,%9}, {%0,%1,%2,%3};"
        : "+f"(d[0]), "+f"(d[1]), "+f"(d[2]), "+f"(d[3])
        : "r"(a[0]), "r"(a[1]), "r"(a[2]), "r"(a[3]), "r"(b[0]), "r"(b[1]));
}

__device__ __forceinline__ void compute_chunk(const uint32_t* sm, int stg, int lane,
                                              int wm, int wn, float acc[4][4][4]){
    const int klo = lane & 3, lq = lane >> 2;
    const int base = stg * STG;
    #pragma unroll
    for (int k8 = 0; k8 < 4; k8++){
        const int a0 = base + (k8*2)*GRP + klo;
        const int b0 = base + AB_OFF + (k8*2)*GRP + klo;
        uint32_t af[4][4], bf[4][2];
        #pragma unroll
        for (int mt = 0; mt < 4; mt++){
            const int mo = (wm + mt*16 + lq) * 4;
            af[mt][0] = sm[a0 + mo];
            af[mt][1] = sm[a0 + mo + 32];
            af[mt][2] = sm[a0 + GRP + mo];
            af[mt][3] = sm[a0 + GRP + mo + 32];
        }
        #pragma unroll
        for (int nt = 0; nt < 4; nt++){
            const int no = (wn + nt*8 + lq) * 4;
            bf[nt][0] = sm[b0 + no];
            bf[nt][1] = sm[b0 + GRP + no];
        }
        #pragma unroll
        for (int mt = 0; mt < 4; mt++)
            #pragma unroll
            for (int nt = 0; nt < 4; nt++)
                mma_tf32(acc[mt][nt], af[mt], bf[nt]);
    }
}

// ---------------- tensor-core GEMM (mma.sync tf32, cp.async 3-stage) ----------------
// D[m, p] = sum_k A[m0+m, k] * B[p, k]
// ZMODE 0: bz=n.  ZMODE 1: bz -> (n,s4,v25) temporal mix.
// BSHIFT: TCN im2col. CM 0: [n][p][ldc]+mg ; CM 1: NCHW out ; CM 2: zT write
template<int ZMODE,int BSHIFT,int CM,bool BIAS,bool BNORM,bool RES,bool LRELU,bool PRED>
__global__ __launch_bounds__(256,2)
void mma_gemm(const float* __restrict__ A, const float* __restrict__ Bp,
              float* __restrict__ Cp,
              const float* __restrict__ bias, const float* __restrict__ gam,
              const float* __restrict__ bet, const float* __restrict__ resT,
              int Ka, int Bld, int ldc, int Mvalid, int nch, int Np)
{
    extern __shared__ uint32_t sm[];
    const uint32_t sbw = smem_u32(sm);
    const int tid = threadIdx.x, lane = tid & 31, wid = tid >> 5;
    const int wm = (wid >> 2) * 64, wn = (wid & 3) * 32;
    const int lq = lane >> 2, klo = lane & 3;

    int n, s4 = 0, v25 = 0;
    if (ZMODE == 0) { n = blockIdx.z; }
    else { int bz = blockIdx.z; n = bz / 100; int rr = bz % 100; s4 = rr / 25; v25 = rr % 25; }
    const int m0 = blockIdx.y * 128;
    const int p0 = (ZMODE == 0) ? blockIdx.x * 128 : 0;
    const float* Ab = (ZMODE == 0) ? A : A + (size_t)(n*4 + s4) * 16384;
    const float* Bb = (ZMODE == 0) ? Bp + (size_t)n * Np * Bld
                                   : Bp + (size_t)(n*25 + v25) * 16384;

    const int r = tid & 127, kh = (tid >> 7) * 16, g0 = (tid >> 7) * 4;
    const float* parow = Ab + (size_t)(m0 + r) * Ka + kh;

    float acc[4][4][4];
    #pragma unroll
    for (int a = 0; a < 4; a++)
        #pragma unroll
        for (int b = 0; b < 4; b++)
            #pragma unroll
            for (int c = 0; c < 4; c++) acc[a][b][c] = 0.f;

#define ISSUE(cc, stg) {                                                         \
        const int k0_ = (cc) * 32;                                               \
        int k0B_, grow_;                                                         \
        if (BSHIFT){ int j_ = (cc) >> 2; k0B_ = ((cc) & 3) * 32;                 \
                     grow_ = p0 + r + (j_ - 3) * 25; }                           \
        else { k0B_ = k0_; grow_ = p0 + r; }                                     \
        const bool ok_ = (!BSHIFT) || ((unsigned)grow_ < (unsigned)TVn);         \
        const int bsz_ = ok_ ? 16 : 0;                                           \
        const float* asrc_ = parow + k0_;                                        \
        const float* bsrc_ = Bb + (size_t)(ok_ ? grow_ : 0) * Bld + k0B_ + kh;   \
        const uint32_t ad_ = sbw + 4u * ((stg) * STG + g0 * GRP + r * 4);        \
        const uint32_t bd_ = ad_ + 4u * AB_OFF;                                  \
        _Pragma("unroll")                                                        \
        for (int i = 0; i < 4; i++){                                             \
            asm volatile("cp.async.cg.shared.global [%0], [%1], 16;"             \
                         :: "r"(ad_ + 4u*i*GRP), "l"(asrc_ + i*4) : "memory");   \
            asm volatile("cp.async.cg.shared.global [%0], [%1], 16, %2;"         \
                         :: "r"(bd_ + 4u*i*GRP), "l"(bsrc_ + i*4), "r"(bsz_) : "memory"); \
        } }

    ISSUE(0, 0)
    asm volatile("cp.async.commit_group;" ::: "memory");
    ISSUE(1, 1)
    asm volatile("cp.async.commit_group;" ::: "memory");

    for (int c = 0; c < nch; c++) {
        asm volatile("cp.async.wait_group 1;" ::: "memory");
        __syncthreads();
        compute_chunk(sm, c % NSTAGE, lane, wm, wn, acc);
        const int nc = c + 2;
        if (nc < nch) { ISSUE(nc, nc % NSTAGE) }
        asm volatile("cp.async.commit_group;" ::: "memory");
    }
#undef ISSUE

    // ---- epilogue: stage through smem for coalesced I/O ----
    asm volatile("cp.async.wait_group 0;" ::: "memory");
    __syncthreads();
    float* smf = reinterpret_cast<float*>(sm);

    #pragma unroll
    for (int mt = 0; mt < 4; mt++)
        #pragma unroll
        for (int h = 0; h < 2; h++)
            #pragma unroll
            for (int nt = 0; nt < 4; nt++)
                #pragma unroll
                for (int q = 0; q < 2; q++) {
                    const int m = wm + mt*16 + lq + h*8;
                    const int col = wn + nt*8 + klo*2 + q;
                    if (CM == 0) smf[col*132 + m] = acc[mt][nt][h*2 + q];
                    else         smf[m*132 + col] = acc[mt][nt][h*2 + q];
                }
    __syncthreads();

    #pragma unroll
    for (int it = 0; it < 16; it++) {
        const int idx = it*256 + tid;
        if (CM == 0) {
            const int col = idx >> 5, m4 = (idx & 31) * 4;
            const int mg0 = m0 + m4;
            if (PRED && mg0 >= Mvalid) continue;
            float4 v4 = *(float4*)&smf[col*132 + m4];
            float vv[4] = {v4.x, v4.y, v4.z, v4.w};
            float4 b4, g4, e4, r4;
            if (BIAS)  b4 = *(const float4*)(bias + mg0);
            if (BNORM){ g4 = *(const float4*)(gam + mg0); e4 = *(const float4*)(bet + mg0); }
            if (RES)   r4 = *(const float4*)(resT + ((size_t)n*Np + p0 + col)*128 + mg0);
            const float* bp = (const float*)&b4; const float* gp = (const float*)&g4;
            const float* ep = (const float*)&e4; const float* rp = (const float*)&r4;
            float4 o4; float* op = (float*)&o4;
            #pragma unroll
            for (int j = 0; j < 4; j++) {
                float v = vv[j];
                if (BIAS)  v += bp[j];
                if (BNORM) v = v * (gp[j] * BN_INV) + ep[j];
                if (RES)   v += rp[j];
                if (LRELU) v = v > 0.f ? v : 0.1f * v;
                op[j] = v;
            }
            *(float4*)(Cp + ((size_t)n*Np + p0 + col)*ldc + mg0) = o4;
        } else {
            const int m = idx >> 5, c4 = (idx & 31) * 4;
            const int mg = m0 + m;
            float4 v4 = *(float4*)&smf[m*132 + c4];
            float vv[4] = {v4.x, v4.y, v4.z, v4.w};
            float bi = BIAS ? bias[mg] : 0.f;
            float sc = BNORM ? gam[mg] * BN_INV : 1.f;
            float sh = BNORM ? bet[mg] : 0.f;
            float4 r4;
            if (CM == 1 && RES)
                r4 = *(const float4*)(resT + ((size_t)(n*128 + mg))*TVn + p0 + c4);
            const float* rp = (const float*)&r4;
            float4 o4; float* op = (float*)&o4;
            #pragma unroll
            for (int j = 0; j < 4; j++) {
                float v = vv[j] + bi;
                if (BNORM) v = v * sc + sh;
                if (CM == 1 && RES) v += rp[j];
                if (LRELU) v = v > 0.f ? v : 0.1f * v;
                op[j] = v;
            }
            if (CM == 1)
                *(float4*)(Cp + ((size_t)(n*128 + mg))*TVn + p0 + c4) = o4;
            else
                *(float4*)(Cp + ((size_t)n*TVn + (size_t)m*25 + v25)*512 + s4*128 + c4) = o4;
        }
    }
}

// ---------------- prep: weight pack ----------------
__global__ void pack_w(const float* __restrict__ src, float* __restrict__ dst,
                       int Msrc, int Mdst, int K, int tcn)
{
    int idx = blockIdx.x * blockDim.x + threadIdx.x;
    if (idx >= Mdst * K) return;
    int mrow = idx / K, k = idx % K;
    float v = 0.f;
    if (mrow < Msrc) {
        if (tcn) { int j = k >> 7, c = k & 127; v = src[(mrow * 128 + c) * 7 + j]; }
        else     { v = src[(size_t)mrow * K + k]; }
    }
    dst[idx] = __uint_as_float(f2tf32(v));
}

// ---------------- prep: x -> xT ----------------
__global__ __launch_bounds__(256) void txpose_x(const float* __restrict__ x)
{
    __shared__ float t[32][33];
    int p0 = blockIdx.x * 32, c0 = blockIdx.y * 32, n = blockIdx.z;
    int tx = threadIdx.x & 31, ty = threadIdx.x >> 5;
    for (int r = ty; r < 32; r += 8)
        t[r][tx] = x[((size_t)n * 128 + c0 + r) * TVn + p0 + tx];
    __syncthreads();
    for (int r = ty; r < 32; r += 8)
        g_xT[(size_t)n * TVn * 128 + (size_t)(p0 + r) * 128 + c0 + tx] = t[tx][r];
}

// ---------------- prep: toT -> tnc (NCHW) ----------------
__global__ __launch_bounds__(256) void txpose_inv()
{
    __shared__ float t[32][33];
    int p0 = blockIdx.x * 32, c0 = blockIdx.y * 32, n = blockIdx.z;
    int tx = threadIdx.x & 31, ty = threadIdx.x >> 5;
    for (int r = ty; r < 32; r += 8)
        t[r][tx] = g_toT[((size_t)n * TVn + p0 + r) * 128 + c0 + tx];
    __syncthreads();
    for (int r = ty; r < 32; r += 8)
        g_tnc[((size_t)n * 128 + c0 + r) * TVn + p0 + tx] = t[tx][r];
}

// ---------------- prep: soT -> tmaj[n][v][c][t] ----------------
__global__ __launch_bounds__(256) void txpose_tmaj()
{
    __shared__ float t[32][33];
    int bt = blockIdx.x;
    int t0 = (bt & 3) * 32, c0 = (bt >> 2) * 32;
    int v = blockIdx.y, n = blockIdx.z;
    int tx = threadIdx.x & 31, ty = threadIdx.x >> 5;
    for (int r = ty; r < 32; r += 8)
        t[r][tx] = g_soT[(size_t)n * TVn * 128 + (size_t)((t0 + r) * 25 + v) * 128 + c0 + tx];
    __syncthreads();
    for (int r = ty; r < 32; r += 8)
        g_tmaj[((size_t)(n * 25 + v) * 128 + c0 + r) * 128 + t0 + tx] = t[tx][r];
}

// ---------------- spatial attention ----------------
__global__ __launch_bounds__(256)
void satt_kernel(const float* __restrict__ att0, const float* __restrict__ alphas)
{
    int t = blockIdx.x, s = blockIdx.y, n = blockIdx.z;
    __shared__ float qs[32][25], ks[32][25];
    int tid = threadIdx.x;
    const float* qb = g_qkT + (size_t)n * TVn * 192;
    for (int i = tid; i < 800; i += 256) {
        int row = i >> 5, c = i & 31;
        qs[c][row] = qb[(size_t)(t * 25 + row) * 192 + s * 32 + c];
        ks[c][row] = qb[(size_t)(t * 25 + row) * 192 + 96 + s * 32 + c];
    }
    __syncthreads();
    float alpha = alphas[s];
    float* ob = g_atts + (((size_t)(n * 3 + s)) * 128 + t) * 625;
    for (int idx = tid; idx < 625; idx += 256) {
        int u = idx / 25, v = idx % 25;
        float sum = 0.f;
        #pragma unroll
        for (int c = 0; c < 32; c++) sum += qs[c][u] * ks[c][v];
        ob[idx] = att0[s * 625 + idx] + tanhf(sum * (1.f / 32.f)) * alpha;
    }
}

// ---------------- spatial mix -> yT ----------------
__global__ __launch_bounds__(128)
void ymix_kernel()
{
    int t = blockIdx.x, s = blockIdx.y, n = blockIdx.z;
    __shared__ float a[625];
    int c = threadIdx.x;
    const float* ab = g_atts + (((size_t)(n * 3 + s)) * 128 + t) * 625;
    for (int i = c; i < 625; i += 128) a[i] = ab[i];
    __syncthreads();
    float xr[25];
    const float* xb = g_xT + (size_t)n * TVn * 128 + (size_t)(t * 25) * 128 + c;
    #pragma unroll
    for (int u = 0; u < 25; u++) xr[u] = xb[u * 128];
    float accv[25] = {};
    #pragma unroll
    for (int u = 0; u < 25; u++) {
        float xu = xr[u];
        #pragma unroll
        for (int v = 0; v < 25; v++) accv[v] += xu * a[u * 25 + v];
    }
    #pragma unroll
    for (int v = 0; v < 25; v++)
        g_yT[(size_t)n * TVn * 384 + (size_t)(t * 25 + v) * 384 + s * 128 + c] = accv[v];
}

// ---------------- mean over V (sout -> sbar[n][t][c]) ----------------
__global__ void meanv_kernel()
{
    int i = blockIdx.x * blockDim.x + threadIdx.x;
    if (i >= NB * 128 * 128) return;
    int c = i & 127, t = (i >> 7) & 127, n = i >> 14;
    const float* b = g_soT + (size_t)n * TVn * 128 + (size_t)(t * 25) * 128 + c;
    float sum = 0.f;
    #pragma unroll
    for (int v = 0; v < 25; v++) sum += b[v * 128];
    g_sbar[(size_t)n * 16384 + t * 128 + c] = sum * (1.f / 25.f);
}

// ---------------- temporal attention -> att[u][t] ----------------
__global__ __launch_bounds__(256)
void tatt_kernel(const float* __restrict__ af, const float* __restrict__ ab)
{
    int bz = blockIdx.x;  // n*4 + s
    int n = bz >> 2, s = bz & 3;
    __shared__ float qs[32][129], ks[32][129];
    int tid = threadIdx.x;
    const float* base = g_qtm + (size_t)n * 32768;   // [t][256]
    for (int i = tid; i < 4096; i += 256) {
        int t = i >> 5, c = i & 31;
        qs[c][t] = base[t * 256 + s * 32 + c];
        ks[c][t] = base[t * 256 + 128 + s * 32 + c];
    }
    __syncthreads();
    float alpha = (s < 2) ? af[s] : ab[s - 2];
    for (int idx = tid; idx < 16384; idx += 256) {
        int u = idx >> 7, t = idx & 127;
        float sum = 0.f;
        #pragma unroll
        for (int c = 0; c < 32; c++) sum += qs[c][t] * ks[c][u];
        float v = tanhf(sum * (1.f / 32.f)) * alpha;
        bool keep = (s < 2) ? (t >= u) : (u >= t);
        g_att[(size_t)bz * 16384 + idx] = keep ? v : 0.f;  // [u][t]
    }
}

// ---------------- host launcher ----------------
extern "C" void kernel_launch(void* const* d_in, const int* in_sizes, int n_in,
                              void* d_out, int out_size)
{
    const float* x       = (const float*)d_in[0];
    const float* w_in_s  = (const float*)d_in[1];
    const float* b_in_s  = (const float*)d_in[2];
    const float* att0s   = (const float*)d_in[3];
    const float* alphas  = (const float*)d_in[4];
    const float* w_out_s = (const float*)d_in[5];
    const float* b_out_s = (const float*)d_in[6];
    const float* g_out_s = (const float*)d_in[7];
    const float* be_out_s= (const float*)d_in[8];
    const float* w_ff_s  = (const float*)d_in[9];
    const float* b_ff_s  = (const float*)d_in[10];
    const float* g_ff_s  = (const float*)d_in[11];
    const float* be_ff_s = (const float*)d_in[12];
    const float* w_in_t  = (const float*)d_in[13];
    const float* b_in_t  = (const float*)d_in[14];
    const float* al_f    = (const float*)d_in[15];
    const float* al_b    = (const float*)d_in[16];
    const float* w_out_t = (const float*)d_in[17];
    const float* b_out_t = (const float*)d_in[18];
    const float* g_out_t = (const float*)d_in[19];
    const float* be_out_t= (const float*)d_in[20];
    const float* w_ff_t  = (const float*)d_in[21];
    const float* b_ff_t  = (const float*)d_in[22];
    const float* g_ff_t  = (const float*)d_in[23];
    const float* be_ff_t = (const float*)d_in[24];
    const float* w_tcn   = (const float*)d_in[25];
    const float* b_tcn   = (const float*)d_in[26];
    const float* g_tcn   = (const float*)d_in[27];
    const float* be_tcn  = (const float*)d_in[28];
    float* out = (float*)d_out;

    float *wp, *xT, *qkT, *yT, *s1T, *soT, *sbar, *qtm, *att, *tmaj, *zT, *toT, *tnc;
    cudaGetSymbolAddress((void**)&wp,   g_wp);
    cudaGetSymbolAddress((void**)&xT,   g_xT);
    cudaGetSymbolAddress((void**)&qkT,  g_qkT);
    cudaGetSymbolAddress((void**)&yT,   g_yT);
    cudaGetSymbolAddress((void**)&s1T,  g_s1T);
    cudaGetSymbolAddress((void**)&soT,  g_soT);
    cudaGetSymbolAddress((void**)&sbar, g_sbar);
    cudaGetSymbolAddress((void**)&qtm,  g_qtm);
    cudaGetSymbolAddress((void**)&att,  g_att);
    cudaGetSymbolAddress((void**)&tmaj, g_tmaj);
    cudaGetSymbolAddress((void**)&zT,   g_zT);
    cudaGetSymbolAddress((void**)&toT,  g_toT);
    cudaGetSymbolAddress((void**)&tnc,  g_tnc);

    auto G1 = mma_gemm<0,0,0,true,false,false,false,true>;   // qk (padded M)
    auto G2 = mma_gemm<0,0,0,true,true,true,true,false>;     // bn+res+lrelu, transposed out
    auto G3 = mma_gemm<0,0,0,true,false,false,false,false>;  // plain bias (qtm)
    auto G4 = mma_gemm<1,0,2,false,false,false,false,false>; // temporal mix
    auto G5 = mma_gemm<0,1,1,true,true,true,true,false>;     // TCN final, NCHW out
    cudaFuncSetAttribute(G1, cudaFuncAttributeMaxDynamicSharedMemorySize, SMEMSZ);
    cudaFuncSetAttribute(G2, cudaFuncAttributeMaxDynamicSharedMemorySize, SMEMSZ);
    cudaFuncSetAttribute(G3, cudaFuncAttributeMaxDynamicSharedMemorySize, SMEMSZ);
    cudaFuncSetAttribute(G4, cudaFuncAttributeMaxDynamicSharedMemorySize, SMEMSZ);
    cudaFuncSetAttribute(G5, cudaFuncAttributeMaxDynamicSharedMemorySize, SMEMSZ);

    // ---- prep ----
    pack_w<<<(256*128+255)/256,256>>>(w_in_s,  wp+OFF_WINS,  192, 256, 128, 0);
    pack_w<<<(128*384+255)/256,256>>>(w_out_s, wp+OFF_WOUTS, 128, 128, 384, 0);
    pack_w<<<(128*128+255)/256,256>>>(w_ff_s,  wp+OFF_WFFS,  128, 128, 128, 0);
    pack_w<<<(256*128+255)/256,256>>>(w_in_t,  wp+OFF_WINT,  256, 256, 128, 0);
    pack_w<<<(128*512+255)/256,256>>>(w_out_t, wp+OFF_WOUTT, 128, 128, 512, 0);
    pack_w<<<(128*128+255)/256,256>>>(w_ff_t,  wp+OFF_WFFT,  128, 128, 128, 0);
    pack_w<<<(128*896+255)/256,256>>>(w_tcn,   wp+OFF_WTCN,  128, 128, 896, 1);
    txpose_x<<<dim3(100,4,NB),256>>>(x);

    // 1) qk = W_in_s @ x + b   (M padded 256, valid 192)
    G1<<<dim3(25,2,NB),256,SMEMSZ>>>(wp+OFF_WINS, xT, qkT,
        b_in_s, nullptr, nullptr, nullptr, 128, 128, 192, 192, 4, TVn);

    // 2) spatial attention
    satt_kernel<<<dim3(128,3,NB),256>>>(att0s, alphas);

    // 3) y = x @ att
    ymix_kernel<<<dim3(128,3,NB),128>>>();

    // 4) s1 = lrelu(x + bn(W_out_s @ y + b))   K=384
    G2<<<dim3(25,1,NB),256,SMEMSZ>>>(wp+OFF_WOUTS, yT, s1T,
        b_out_s, g_out_s, be_out_s, xT, 384, 384, 128, 128, 12, TVn);

    // 5) sout = lrelu(x + bn(W_ff_s @ s1 + b))
    G2<<<dim3(25,1,NB),256,SMEMSZ>>>(wp+OFF_WFFS, s1T, soT,
        b_ff_s, g_ff_s, be_ff_s, xT, 128, 128, 128, 128, 4, TVn);

    // 6) qtm = W_in_t @ mean_v(sout) + b   (mean commutes with conv1x1)
    meanv_kernel<<<(NB*128*128+255)/256,256>>>();
    G3<<<dim3(1,2,NB),256,SMEMSZ>>>(wp+OFF_WINT, sbar, qtm,
        b_in_t, nullptr, nullptr, nullptr, 128, 128, 256, 256, 4, 128);

    // 7) temporal attention
    tatt_kernel<<<NB*4,256>>>(al_f, al_b);

    // prep: sout -> tmaj
    txpose_tmaj<<<dim3(16,25,NB),256>>>();

    // 8) z (temporal mix) per (n,s,v)
    G4<<<dim3(1,1,NB*100),256,SMEMSZ>>>(att, tmaj, zT,
        nullptr, nullptr, nullptr, nullptr, 128, 128, 512, 128, 4, TVn);

    // 9) t1 = lrelu(sout + bn(W_out_t @ z + b))   K=512
    G2<<<dim3(25,1,NB),256,SMEMSZ>>>(wp+OFF_WOUTT, zT, s1T,
        b_out_t, g_out_t, be_out_t, soT, 512, 512, 128, 128, 16, TVn);

    // 10) tout = lrelu(sout + bn(W_ff_t @ t1 + b))
    G2<<<dim3(25,1,NB),256,SMEMSZ>>>(wp+OFF_WFFT, s1T, toT,
        b_ff_t, g_ff_t, be_ff_t, soT, 128, 128, 128, 128, 4, TVn);

    // prep: toT -> NCHW copy for final residual
    txpose_inv<<<dim3(100,4,NB),256>>>();

    // 11) out = lrelu(tout + bn(tcn7(tout)+b))   K=896 im2col
    G5<<<dim3(25,1,NB),256,SMEMSZ>>>(wp+OFF_WTCN, toT, out,
        b_tcn, g_tcn, be_tcn, tnc, 896, 128, 128, 128, 28, TVn);
}